// round 1
// baseline (speedup 1.0000x reference)
#include <cuda_runtime.h>
#include <stdint.h>

// ---- problem constants ----
#define NTOK 2048
#define DDIM 512
#define GRP  8
#define NQH  8
#define AD1  128
#define AD2  64

// ---- scratch (device globals: allocation-free) ----
__device__ float g_K1[GRP*NTOK*AD1];
__device__ float g_V1[GRP*NTOK*AD1];
__device__ float g_S1[GRP*AD1*AD1];
__device__ float g_P1[GRP*DDIM*NQH*AD1];
__device__ float g_bP1[GRP*NQH*AD1];
__device__ float g_W1[GRP*DDIM*DDIM];
__device__ float g_b1[GRP*DDIM];
__device__ float g_o1[GRP*NTOK*DDIM];
__device__ float g_K2[GRP*NTOK*AD2];
__device__ float g_V2[GRP*NTOK*AD2];
__device__ float g_S2[GRP*AD2*AD2];
__device__ float g_P2[GRP*DDIM*NQH*AD2];
__device__ float g_bP2[GRP*NQH*AD2];
__device__ float g_W2[GRP*DDIM*DDIM];
__device__ float g_b2[GRP*DDIM];
__device__ float g_W3[GRP*DDIM*DDIM];
__device__ float g_b3[GRP*DDIM];

// ============================================================================
// Batched SGEMM, NN, 128x128 tile, BK=8, 256 threads, 8x8 microtile.
// A row stride = K, B row stride = N, C row stride = ldc.
// Per-batch offsets: off = (b>>bshift)*outer + (b & ((1<<bshift)-1))*inner.
// C = alpha * A@B + bias (bias broadcast over rows, optional).
// ============================================================================
__global__ __launch_bounds__(256, 2)
void gemm_nn_128(const float* __restrict__ A, long long aO, long long aI,
                 const float* __restrict__ B, long long bO, long long bI,
                 const float* __restrict__ bias, long long biasO,
                 float* __restrict__ C, long long cO, long long cI, int ldc,
                 int N, int K, float alpha, int bshift)
{
    int b  = blockIdx.z;
    int bh = b >> bshift;
    int bl = b & ((1 << bshift) - 1);
    const float* Ab = A + (long long)bh * aO + (long long)bl * aI;
    const float* Bb = B + (long long)bh * bO + (long long)bl * bI;
    float*       Cb = C + (long long)bh * cO + (long long)bl * cI;

    __shared__ float As[8][128];
    __shared__ float Bs[8][128];

    int tid = threadIdx.x;
    int m0 = blockIdx.y * 128;
    int n0 = blockIdx.x * 128;

    int arow = tid >> 1;         // 0..127
    int acol = (tid & 1) * 4;    // 0 or 4
    int brow = tid >> 5;         // 0..7
    int bcol = (tid & 31) * 4;   // 0..124
    int tx = tid & 15;
    int ty = tid >> 4;

    const float* Ap = Ab + (long long)(m0 + arow) * K + acol;
    const float* Bp = Bb + (long long)brow * N + n0 + bcol;

    float acc[8][8];
#pragma unroll
    for (int i = 0; i < 8; i++)
#pragma unroll
        for (int j = 0; j < 8; j++) acc[i][j] = 0.f;

    for (int k0 = 0; k0 < K; k0 += 8) {
        float4 av = *(const float4*)(Ap + k0);
        As[acol + 0][arow] = av.x;
        As[acol + 1][arow] = av.y;
        As[acol + 2][arow] = av.z;
        As[acol + 3][arow] = av.w;
        *(float4*)&Bs[brow][bcol] = *(const float4*)(Bp + (long long)k0 * N);
        __syncthreads();
#pragma unroll
        for (int kk = 0; kk < 8; kk++) {
            float4 a0 = *(const float4*)&As[kk][ty * 4];
            float4 a1 = *(const float4*)&As[kk][64 + ty * 4];
            float4 b0 = *(const float4*)&Bs[kk][tx * 4];
            float4 b1 = *(const float4*)&Bs[kk][64 + tx * 4];
            float a[8]  = {a0.x, a0.y, a0.z, a0.w, a1.x, a1.y, a1.z, a1.w};
            float bb[8] = {b0.x, b0.y, b0.z, b0.w, b1.x, b1.y, b1.z, b1.w};
#pragma unroll
            for (int i = 0; i < 8; i++)
#pragma unroll
                for (int j = 0; j < 8; j++)
                    acc[i][j] = fmaf(a[i], bb[j], acc[i][j]);
        }
        __syncthreads();
    }

    float bv[8] = {0, 0, 0, 0, 0, 0, 0, 0};
    if (bias) {
        const float* bp = bias + (long long)bh * biasO;
#pragma unroll
        for (int j = 0; j < 4; j++) {
            bv[j]     = bp[n0 + tx * 4 + j];
            bv[4 + j] = bp[n0 + 64 + tx * 4 + j];
        }
    }
#pragma unroll
    for (int i = 0; i < 8; i++) {
        int row = m0 + ((i < 4) ? (ty * 4 + i) : (64 + ty * 4 + (i - 4)));
        float4 v0, v1;
        v0.x = acc[i][0] * alpha + bv[0];
        v0.y = acc[i][1] * alpha + bv[1];
        v0.z = acc[i][2] * alpha + bv[2];
        v0.w = acc[i][3] * alpha + bv[3];
        v1.x = acc[i][4] * alpha + bv[4];
        v1.y = acc[i][5] * alpha + bv[5];
        v1.z = acc[i][6] * alpha + bv[6];
        v1.w = acc[i][7] * alpha + bv[7];
        *(float4*)&Cb[(long long)row * ldc + n0 + tx * 4]      = v0;
        *(float4*)&Cb[(long long)row * ldc + n0 + 64 + tx * 4] = v1;
    }
}

// ============================================================================
// Batched SGEMM, NN, 64x64 tile, BK=16, 256 threads, 4x4 microtile.
// ============================================================================
__global__ __launch_bounds__(256)
void gemm_nn_64(const float* __restrict__ A, long long aO, long long aI,
                const float* __restrict__ B, long long bO, long long bI,
                const float* __restrict__ bias, long long biasO,
                float* __restrict__ C, long long cO, long long cI, int ldc,
                int N, int K, float alpha, int bshift)
{
    int b  = blockIdx.z;
    int bh = b >> bshift;
    int bl = b & ((1 << bshift) - 1);
    const float* Ab = A + (long long)bh * aO + (long long)bl * aI;
    const float* Bb = B + (long long)bh * bO + (long long)bl * bI;
    float*       Cb = C + (long long)bh * cO + (long long)bl * cI;

    __shared__ float As[16][64];
    __shared__ float Bs[16][64];

    int tid = threadIdx.x;
    int m0 = blockIdx.y * 64;
    int n0 = blockIdx.x * 64;

    int arow = tid >> 2;         // 0..63
    int acol = (tid & 3) * 4;    // 0,4,8,12
    int brow = tid >> 4;         // 0..15
    int bcol = (tid & 15) * 4;   // 0..60
    int tx = tid & 15;
    int ty = tid >> 4;

    const float* Ap = Ab + (long long)(m0 + arow) * K + acol;
    const float* Bp = Bb + (long long)brow * N + n0 + bcol;

    float acc[4][4];
#pragma unroll
    for (int i = 0; i < 4; i++)
#pragma unroll
        for (int j = 0; j < 4; j++) acc[i][j] = 0.f;

    for (int k0 = 0; k0 < K; k0 += 16) {
        float4 av = *(const float4*)(Ap + k0);
        As[acol + 0][arow] = av.x;
        As[acol + 1][arow] = av.y;
        As[acol + 2][arow] = av.z;
        As[acol + 3][arow] = av.w;
        *(float4*)&Bs[brow][bcol] = *(const float4*)(Bp + (long long)k0 * N);
        __syncthreads();
#pragma unroll
        for (int kk = 0; kk < 16; kk++) {
            float4 a = *(const float4*)&As[kk][ty * 4];
            float4 bb4 = *(const float4*)&Bs[kk][tx * 4];
            float a4[4]  = {a.x, a.y, a.z, a.w};
            float b4[4]  = {bb4.x, bb4.y, bb4.z, bb4.w};
#pragma unroll
            for (int i = 0; i < 4; i++)
#pragma unroll
                for (int j = 0; j < 4; j++)
                    acc[i][j] = fmaf(a4[i], b4[j], acc[i][j]);
        }
        __syncthreads();
    }

    float bv[4] = {0, 0, 0, 0};
    if (bias) {
        const float* bp = bias + (long long)bh * biasO;
#pragma unroll
        for (int j = 0; j < 4; j++) bv[j] = bp[n0 + tx * 4 + j];
    }
#pragma unroll
    for (int i = 0; i < 4; i++) {
        int row = m0 + ty * 4 + i;
        float4 v;
        v.x = acc[i][0] * alpha + bv[0];
        v.y = acc[i][1] * alpha + bv[1];
        v.z = acc[i][2] * alpha + bv[2];
        v.w = acc[i][3] * alpha + bv[3];
        *(float4*)&Cb[(long long)row * ldc + n0 + tx * 4] = v;
    }
}

// ============================================================================
// Batched SGEMM, TN (C = alpha * A^T @ B), A is KxM row-major, B is KxN.
// 64x64 tile, BK=16, 256 threads, 4x4 microtile. No bias.
// ============================================================================
__global__ __launch_bounds__(256)
void gemm_tn_64(const float* __restrict__ A, long long aO,
                const float* __restrict__ B, long long bO,
                float* __restrict__ C, long long cO, int ldc,
                int M, int N, int K, float alpha)
{
    int b = blockIdx.z;
    const float* Ab = A + (long long)b * aO;
    const float* Bb = B + (long long)b * bO;
    float*       Cb = C + (long long)b * cO;

    __shared__ float As[16][64];
    __shared__ float Bs[16][64];

    int tid = threadIdx.x;
    int m0 = blockIdx.y * 64;
    int n0 = blockIdx.x * 64;

    int lrow = tid >> 4;         // 0..15
    int lcol = (tid & 15) * 4;   // 0..60
    int tx = tid & 15;
    int ty = tid >> 4;

    const float* Ap = Ab + (long long)lrow * M + m0 + lcol;
    const float* Bp = Bb + (long long)lrow * N + n0 + lcol;

    float acc[4][4];
#pragma unroll
    for (int i = 0; i < 4; i++)
#pragma unroll
        for (int j = 0; j < 4; j++) acc[i][j] = 0.f;

    for (int k0 = 0; k0 < K; k0 += 16) {
        *(float4*)&As[lrow][lcol] = *(const float4*)(Ap + (long long)k0 * M);
        *(float4*)&Bs[lrow][lcol] = *(const float4*)(Bp + (long long)k0 * N);
        __syncthreads();
#pragma unroll
        for (int kk = 0; kk < 16; kk++) {
            float4 a = *(const float4*)&As[kk][ty * 4];
            float4 bb4 = *(const float4*)&Bs[kk][tx * 4];
            float a4[4] = {a.x, a.y, a.z, a.w};
            float b4[4] = {bb4.x, bb4.y, bb4.z, bb4.w};
#pragma unroll
            for (int i = 0; i < 4; i++)
#pragma unroll
                for (int j = 0; j < 4; j++)
                    acc[i][j] = fmaf(a4[i], b4[j], acc[i][j]);
        }
        __syncthreads();
    }

#pragma unroll
    for (int i = 0; i < 4; i++) {
        int row = m0 + ty * 4 + i;
        float4 v;
        v.x = acc[i][0] * alpha;
        v.y = acc[i][1] * alpha;
        v.z = acc[i][2] * alpha;
        v.w = acc[i][3] * alpha;
        *(float4*)&Cb[(long long)row * ldc + n0 + tx * 4] = v;
    }
}

// ============================================================================
// Batched vec @ mat: out[b] = vec[b] @ mat[b'] (+ add[b]).
// mat row stride = N; mat batch offset = (b>>bshift)*matO + (b&mask)*matI.
// ============================================================================
__global__ void vecmat(const float* __restrict__ vec, long long vecStride,
                       const float* __restrict__ mat, long long matO, long long matI, int bshift,
                       const float* __restrict__ add, long long addStride,
                       float* __restrict__ out, long long outStride,
                       int K, int N)
{
    int b = blockIdx.y;
    int col = blockIdx.x * blockDim.x + threadIdx.x;
    if (col >= N) return;
    const float* v = vec + (long long)b * vecStride;
    const float* m = mat + (long long)(b >> bshift) * matO
                         + (long long)(b & ((1 << bshift) - 1)) * matI;
    float s = 0.f;
    for (int k = 0; k < K; k++)
        s = fmaf(v[k], m[(long long)k * N + col], s);
    if (add) s += add[(long long)b * addStride + col];
    out[(long long)b * outStride + col] = s;
}

// ============================================================================
// Launch sequence.
//
// Math (no softmax => reassociate):
//   S1[g]      = (K1^T V1)/sqrt(A1),          K1 = x Wk1[g]+bk1, V1 = x Wv1[g]+bv1
//   P1cat[g]   = [Wq1[g,0] S1 | ... | Wq1[g,7] S1]           ([D, NQ*A1])
//   Weff1[g]   = P1cat[g] @ Wo1[g]                            ([D, D])
//   beff1[g]   = concat_q(bq1[g,q] S1) @ Wo1[g] + bo1[g]
//   o1[g]      = x @ Weff1[g] + beff1[g]
// tier 2 identical on o1[g]; final Wo folds: Weff3[g]=Weff2[g]@Wo,
//   out[g]     = o1[g] @ Weff3[g] + (beff2[g]@Wo + bo)
// ============================================================================
extern "C" void kernel_launch(void* const* d_in, const int* in_sizes, int n_in,
                              void* d_out, int out_size)
{
    (void)in_sizes; (void)n_in; (void)out_size;

    const float* x   = (const float*)d_in[0];
    const float* Wq1 = (const float*)d_in[1];
    const float* bq1 = (const float*)d_in[2];
    const float* Wk1 = (const float*)d_in[3];
    const float* bk1 = (const float*)d_in[4];
    const float* Wv1 = (const float*)d_in[5];
    const float* bv1 = (const float*)d_in[6];
    const float* Wo1 = (const float*)d_in[7];
    const float* bo1 = (const float*)d_in[8];
    const float* Wq2 = (const float*)d_in[9];
    const float* bq2 = (const float*)d_in[10];
    const float* Wk2 = (const float*)d_in[11];
    const float* bk2 = (const float*)d_in[12];
    const float* Wv2 = (const float*)d_in[13];
    const float* bv2 = (const float*)d_in[14];
    const float* Wo2 = (const float*)d_in[15];
    const float* bo2 = (const float*)d_in[16];
    const float* Wo  = (const float*)d_in[17];
    const float* bo  = (const float*)d_in[18];
    float* out = (float*)d_out;

    float *K1, *V1, *S1, *P1, *bP1, *W1, *b1, *o1;
    float *K2, *V2, *S2, *P2, *bP2, *W2, *b2, *W3, *b3;
    cudaGetSymbolAddress((void**)&K1,  g_K1);
    cudaGetSymbolAddress((void**)&V1,  g_V1);
    cudaGetSymbolAddress((void**)&S1,  g_S1);
    cudaGetSymbolAddress((void**)&P1,  g_P1);
    cudaGetSymbolAddress((void**)&bP1, g_bP1);
    cudaGetSymbolAddress((void**)&W1,  g_W1);
    cudaGetSymbolAddress((void**)&b1,  g_b1);
    cudaGetSymbolAddress((void**)&o1,  g_o1);
    cudaGetSymbolAddress((void**)&K2,  g_K2);
    cudaGetSymbolAddress((void**)&V2,  g_V2);
    cudaGetSymbolAddress((void**)&S2,  g_S2);
    cudaGetSymbolAddress((void**)&P2,  g_P2);
    cudaGetSymbolAddress((void**)&bP2, g_bP2);
    cudaGetSymbolAddress((void**)&W2,  g_W2);
    cudaGetSymbolAddress((void**)&b2,  g_b2);
    cudaGetSymbolAddress((void**)&W3,  g_W3);
    cudaGetSymbolAddress((void**)&b3,  g_b3);

    const float inv_sa1 = 0.08838834764831845f;  // 1/sqrt(128)
    const float inv_sa2 = 0.125f;                // 1/sqrt(64)

    // -------- tier 1 --------
    // K1[g] = x @ Wk1[g] + bk1[g]   [2048,128]
    gemm_nn_128<<<dim3(1, 16, 8), 256>>>(x, 0, 0,
                                         Wk1, (long long)DDIM*AD1, 0,
                                         bk1, AD1,
                                         K1, (long long)NTOK*AD1, 0, AD1,
                                         AD1, DDIM, 1.f, 0);
    // V1[g]
    gemm_nn_128<<<dim3(1, 16, 8), 256>>>(x, 0, 0,
                                         Wv1, (long long)DDIM*AD1, 0,
                                         bv1, AD1,
                                         V1, (long long)NTOK*AD1, 0, AD1,
                                         AD1, DDIM, 1.f, 0);
    // S1[g] = K1^T V1 / sqrt(A1)    [128,128]
    gemm_tn_64<<<dim3(2, 2, 8), 256>>>(K1, (long long)NTOK*AD1,
                                       V1, (long long)NTOK*AD1,
                                       S1, (long long)AD1*AD1, AD1,
                                       AD1, AD1, NTOK, inv_sa1);
    // bP1[g, q*A1:..] = bq1[g,q] @ S1[g]
    vecmat<<<dim3(1, 64), 256>>>(bq1, AD1,
                                 S1, (long long)AD1*AD1, 0, 3,
                                 (const float*)nullptr, 0,
                                 bP1, AD1, AD1, AD1);
    // P1cat[g][:, q*A1:..] = Wq1[g,q] @ S1[g]   [512,128] x 64 batches
    gemm_nn_128<<<dim3(1, 4, 64), 256>>>(Wq1, (long long)NQH*DDIM*AD1, (long long)DDIM*AD1,
                                         S1, (long long)AD1*AD1, 0,
                                         (const float*)nullptr, 0,
                                         P1, (long long)DDIM*NQH*AD1, AD1, NQH*AD1,
                                         AD1, AD1, 1.f, 3);
    // beff1[g] = bP1[g] @ Wo1[g] + bo1[g]
    vecmat<<<dim3(2, 8), 256>>>(bP1, NQH*AD1,
                                Wo1, (long long)NQH*AD1*DDIM, 0, 0,
                                bo1, DDIM,
                                b1, DDIM, NQH*AD1, DDIM);
    // Weff1[g] = P1cat[g] @ Wo1[g]   [512,512] K=1024
    gemm_nn_128<<<dim3(4, 4, 8), 256>>>(P1, (long long)DDIM*NQH*AD1, 0,
                                        Wo1, (long long)NQH*AD1*DDIM, 0,
                                        (const float*)nullptr, 0,
                                        W1, (long long)DDIM*DDIM, 0, DDIM,
                                        DDIM, NQH*AD1, 1.f, 0);
    // o1[g] = x @ Weff1[g] + beff1[g]   [2048,512]
    gemm_nn_128<<<dim3(4, 16, 8), 256>>>(x, 0, 0,
                                         W1, (long long)DDIM*DDIM, 0,
                                         b1, DDIM,
                                         o1, (long long)NTOK*DDIM, 0, DDIM,
                                         DDIM, DDIM, 1.f, 0);

    // -------- tier 2 --------
    gemm_nn_64<<<dim3(1, 32, 8), 256>>>(o1, (long long)NTOK*DDIM, 0,
                                        Wk2, (long long)DDIM*AD2, 0,
                                        bk2, AD2,
                                        K2, (long long)NTOK*AD2, 0, AD2,
                                        AD2, DDIM, 1.f, 0);
    gemm_nn_64<<<dim3(1, 32, 8), 256>>>(o1, (long long)NTOK*DDIM, 0,
                                        Wv2, (long long)DDIM*AD2, 0,
                                        bv2, AD2,
                                        V2, (long long)NTOK*AD2, 0, AD2,
                                        AD2, DDIM, 1.f, 0);
    gemm_tn_64<<<dim3(1, 1, 8), 256>>>(K2, (long long)NTOK*AD2,
                                       V2, (long long)NTOK*AD2,
                                       S2, (long long)AD2*AD2, AD2,
                                       AD2, AD2, NTOK, inv_sa2);
    vecmat<<<dim3(1, 64), 256>>>(bq2, AD2,
                                 S2, (long long)AD2*AD2, 0, 3,
                                 (const float*)nullptr, 0,
                                 bP2, AD2, AD2, AD2);
    gemm_nn_64<<<dim3(1, 8, 64), 256>>>(Wq2, (long long)NQH*DDIM*AD2, (long long)DDIM*AD2,
                                        S2, (long long)AD2*AD2, 0,
                                        (const float*)nullptr, 0,
                                        P2, (long long)DDIM*NQH*AD2, AD2, NQH*AD2,
                                        AD2, AD2, 1.f, 3);
    vecmat<<<dim3(2, 8), 256>>>(bP2, NQH*AD2,
                                Wo2, (long long)NQH*AD2*DDIM, 0, 0,
                                bo2, DDIM,
                                b2, DDIM, NQH*AD2, DDIM);
    // Weff2[g] = P2cat[g] @ Wo2[g]
    gemm_nn_128<<<dim3(4, 4, 8), 256>>>(P2, (long long)DDIM*NQH*AD2, 0,
                                        Wo2, (long long)NQH*AD2*DDIM, 0,
                                        (const float*)nullptr, 0,
                                        W2, (long long)DDIM*DDIM, 0, DDIM,
                                        DDIM, NQH*AD2, 1.f, 0);
    // b3[g] = beff2[g] @ Wo + bo
    vecmat<<<dim3(2, 8), 256>>>(b2, DDIM,
                                Wo, 0, 0, 0,
                                bo, 0,
                                b3, DDIM, DDIM, DDIM);
    // Weff3[g] = Weff2[g] @ Wo
    gemm_nn_128<<<dim3(4, 4, 8), 256>>>(W2, (long long)DDIM*DDIM, 0,
                                        Wo, 0, 0,
                                        (const float*)nullptr, 0,
                                        W3, (long long)DDIM*DDIM, 0, DDIM,
                                        DDIM, DDIM, 1.f, 0);
    // out[g] = o1[g] @ Weff3[g] + b3[g]   -> d_out rows [g*2048, (g+1)*2048)
    gemm_nn_128<<<dim3(4, 16, 8), 256>>>(o1, (long long)NTOK*DDIM, 0,
                                         W3, (long long)DDIM*DDIM, 0,
                                         b3, DDIM,
                                         out, (long long)NTOK*DDIM, 0, DDIM,
                                         DDIM, DDIM, 1.f, 0);
}

// round 2
// speedup vs baseline: 1.2113x; 1.2113x over previous
#include <cuda_runtime.h>
#include <stdint.h>

// ---- problem constants ----
#define NTOK 2048
#define DDIM 512
#define GRP  8
#define NQH  8
#define AD1  128
#define AD2  64

// ---- scratch (device globals: allocation-free) ----
__device__ float g_K1[GRP*NTOK*AD1];
__device__ float g_V1[GRP*NTOK*AD1];
__device__ float g_S1[GRP*AD1*AD1];
__device__ float g_P1[GRP*DDIM*NQH*AD1];
__device__ float g_bP1[GRP*NQH*AD1];
__device__ float g_W1[GRP*DDIM*DDIM];
__device__ float g_b1[GRP*DDIM];
__device__ float g_Wk2e[GRP*DDIM*AD2];
__device__ float g_Wv2e[GRP*DDIM*AD2];
__device__ float g_bk2e[GRP*AD2];
__device__ float g_bv2e[GRP*AD2];
__device__ float g_K2[GRP*NTOK*AD2];
__device__ float g_V2[GRP*NTOK*AD2];
__device__ float g_S2[GRP*AD2*AD2];
__device__ float g_bP2[GRP*NQH*AD2];
__device__ float g_P2[GRP*DDIM*NQH*AD2];
__device__ float g_b2[GRP*DDIM];
__device__ float g_W2[GRP*DDIM*DDIM];
__device__ float g_W23[GRP*DDIM*DDIM];
__device__ float g_Wf[GRP*DDIM*DDIM];
__device__ float g_b3[GRP*DDIM];
__device__ float g_bf[GRP*DDIM];

__device__ __forceinline__ float lo32(unsigned long long v) {
    return __uint_as_float((unsigned)(v & 0xffffffffULL));
}
__device__ __forceinline__ float hi32(unsigned long long v) {
    return __uint_as_float((unsigned)(v >> 32));
}
#define FMA2(acc, a, b) \
    asm("fma.rn.f32x2 %0, %1, %2, %0;" : "+l"(acc) : "l"(a), "l"(b))

// ============================================================================
// Packed-fp32x2 batched SGEMM, NN, 128x128 tile, BK=8, 256 threads,
// 8x8 microtile, double-buffered smem, duplicated-A layout.
// A row stride = K, B row stride = N, C row stride = ldc. alpha = 1.
// Batch offsets: off = (b>>bshift)*Outer + (b & mask)*Inner.
// ============================================================================
__global__ __launch_bounds__(256, 2)
void gemm128p(const float* __restrict__ A, long long aO, long long aI,
              const float* __restrict__ B, long long bO, long long bI,
              const float* __restrict__ bias, long long biasO,
              float* __restrict__ C, long long cO, long long cI, int ldc,
              int N, int K, int bshift)
{
    int b  = blockIdx.z;
    int bh = b >> bshift;
    int bl = b & ((1 << bshift) - 1);
    const float* Ab = A + (long long)bh * aO + (long long)bl * aI;
    const float* Bb = B + (long long)bh * bO + (long long)bl * bI;
    float*       Cb = C + (long long)bh * cO + (long long)bl * cI;

    __shared__ __align__(16) float Asd[2][8][256];  // each row value duplicated
    __shared__ __align__(16) float Bs[2][8][128];

    int tid = threadIdx.x;
    int m0 = blockIdx.y * 128;
    int n0 = blockIdx.x * 128;

    int arow = tid >> 1;         // 0..127
    int acol = (tid & 1) * 4;    // 0 or 4
    int brow = tid >> 5;         // 0..7
    int bcol = (tid & 31) * 4;   // 0..124
    int tx = tid & 15;
    int ty = tid >> 4;

    const float* Ap = Ab + (long long)(m0 + arow) * K + acol;
    const float* Bp = Bb + (long long)brow * N + n0 + bcol;

    unsigned long long acc[8][4];
#pragma unroll
    for (int i = 0; i < 8; i++)
#pragma unroll
        for (int j = 0; j < 4; j++) acc[i][j] = 0ULL;

    // prologue: load k-block 0 into buffer 0
    {
        float4 a4 = *(const float4*)Ap;
        float4 b4 = *(const float4*)Bp;
        *(float2*)&Asd[0][acol + 0][2 * arow] = make_float2(a4.x, a4.x);
        *(float2*)&Asd[0][acol + 1][2 * arow] = make_float2(a4.y, a4.y);
        *(float2*)&Asd[0][acol + 2][2 * arow] = make_float2(a4.z, a4.z);
        *(float2*)&Asd[0][acol + 3][2 * arow] = make_float2(a4.w, a4.w);
        *(float4*)&Bs[0][brow][bcol] = b4;
    }
    __syncthreads();

    int cur = 0;
    for (int k0 = 0; k0 < K; k0 += 8) {
        bool more = (k0 + 8) < K;
        float4 aN, bN;
        if (more) {
            aN = *(const float4*)(Ap + k0 + 8);
            bN = *(const float4*)(Bp + (long long)(k0 + 8) * N);
        }
#pragma unroll
        for (int kk = 0; kk < 8; kk++) {
            const float* ar = &Asd[cur][kk][0];
            const float* br = &Bs[cur][kk][0];
            ulonglong2 a01 = *(const ulonglong2*)(ar + 2 * (ty * 4));
            ulonglong2 a23 = *(const ulonglong2*)(ar + 2 * (ty * 4) + 4);
            ulonglong2 a45 = *(const ulonglong2*)(ar + 128 + 2 * (ty * 4));
            ulonglong2 a67 = *(const ulonglong2*)(ar + 128 + 2 * (ty * 4) + 4);
            ulonglong2 q0  = *(const ulonglong2*)(br + tx * 4);
            ulonglong2 q1  = *(const ulonglong2*)(br + 64 + tx * 4);
            unsigned long long av[8] = {a01.x, a01.y, a23.x, a23.y,
                                        a45.x, a45.y, a67.x, a67.y};
            unsigned long long bv[4] = {q0.x, q0.y, q1.x, q1.y};
#pragma unroll
            for (int i = 0; i < 8; i++)
#pragma unroll
                for (int j = 0; j < 4; j++)
                    FMA2(acc[i][j], av[i], bv[j]);
        }
        if (more) {
            int nxt = cur ^ 1;
            *(float2*)&Asd[nxt][acol + 0][2 * arow] = make_float2(aN.x, aN.x);
            *(float2*)&Asd[nxt][acol + 1][2 * arow] = make_float2(aN.y, aN.y);
            *(float2*)&Asd[nxt][acol + 2][2 * arow] = make_float2(aN.z, aN.z);
            *(float2*)&Asd[nxt][acol + 3][2 * arow] = make_float2(aN.w, aN.w);
            *(float4*)&Bs[nxt][brow][bcol] = bN;
        }
        __syncthreads();
        cur ^= 1;
    }

    float bvv[8] = {0, 0, 0, 0, 0, 0, 0, 0};
    if (bias) {
        const float* bp = bias + (long long)bh * biasO;
#pragma unroll
        for (int j = 0; j < 4; j++) {
            bvv[j]     = bp[n0 + tx * 4 + j];
            bvv[4 + j] = bp[n0 + 64 + tx * 4 + j];
        }
    }
#pragma unroll
    for (int i = 0; i < 8; i++) {
        int row = m0 + ((i < 4) ? (ty * 4 + i) : (64 + ty * 4 + (i - 4)));
        float4 v0, v1;
        v0.x = lo32(acc[i][0]) + bvv[0];
        v0.y = hi32(acc[i][0]) + bvv[1];
        v0.z = lo32(acc[i][1]) + bvv[2];
        v0.w = hi32(acc[i][1]) + bvv[3];
        v1.x = lo32(acc[i][2]) + bvv[4];
        v1.y = hi32(acc[i][2]) + bvv[5];
        v1.z = lo32(acc[i][3]) + bvv[6];
        v1.w = hi32(acc[i][3]) + bvv[7];
        *(float4*)&Cb[(long long)row * ldc + n0 + tx * 4]      = v0;
        *(float4*)&Cb[(long long)row * ldc + n0 + 64 + tx * 4] = v1;
    }
}

// ============================================================================
// Packed-fp32x2 batched SGEMM, NN, 128x64 tile, BK=8, 256 threads,
// 8x4 microtile, double-buffered, duplicated-A layout.
// ============================================================================
__global__ __launch_bounds__(256, 2)
void gemm64w(const float* __restrict__ A, long long aO, long long aI,
             const float* __restrict__ B, long long bO, long long bI,
             const float* __restrict__ bias, long long biasO,
             float* __restrict__ C, long long cO, long long cI, int ldc,
             int N, int K, int bshift)
{
    int b  = blockIdx.z;
    int bh = b >> bshift;
    int bl = b & ((1 << bshift) - 1);
    const float* Ab = A + (long long)bh * aO + (long long)bl * aI;
    const float* Bb = B + (long long)bh * bO + (long long)bl * bI;
    float*       Cb = C + (long long)bh * cO + (long long)bl * cI;

    __shared__ __align__(16) float Asd[2][8][256];
    __shared__ __align__(16) float Bs[2][8][64];

    int tid = threadIdx.x;
    int m0 = blockIdx.y * 128;
    int n0 = blockIdx.x * 64;

    int arow = tid >> 1;         // 0..127
    int acol = (tid & 1) * 4;
    int brow = tid >> 5;         // 0..7
    int bcol = (tid & 31) * 2;   // 0..62
    int tx = tid & 15;           // col group
    int ty = tid >> 4;           // 0..15, rows ty*8..ty*8+7

    const float* Ap = Ab + (long long)(m0 + arow) * K + acol;
    const float* Bp = Bb + (long long)brow * N + n0 + bcol;

    unsigned long long acc[8][2];
#pragma unroll
    for (int i = 0; i < 8; i++) { acc[i][0] = 0ULL; acc[i][1] = 0ULL; }

    {
        float4 a4 = *(const float4*)Ap;
        float2 b2 = *(const float2*)Bp;
        *(float2*)&Asd[0][acol + 0][2 * arow] = make_float2(a4.x, a4.x);
        *(float2*)&Asd[0][acol + 1][2 * arow] = make_float2(a4.y, a4.y);
        *(float2*)&Asd[0][acol + 2][2 * arow] = make_float2(a4.z, a4.z);
        *(float2*)&Asd[0][acol + 3][2 * arow] = make_float2(a4.w, a4.w);
        *(float2*)&Bs[0][brow][bcol] = b2;
    }
    __syncthreads();

    int cur = 0;
    for (int k0 = 0; k0 < K; k0 += 8) {
        bool more = (k0 + 8) < K;
        float4 aN; float2 bN;
        if (more) {
            aN = *(const float4*)(Ap + k0 + 8);
            bN = *(const float2*)(Bp + (long long)(k0 + 8) * N);
        }
#pragma unroll
        for (int kk = 0; kk < 8; kk++) {
            const float* ar = &Asd[cur][kk][0];
            const float* br = &Bs[cur][kk][0];
            ulonglong2 a01 = *(const ulonglong2*)(ar + 2 * (ty * 8));
            ulonglong2 a23 = *(const ulonglong2*)(ar + 2 * (ty * 8) + 4);
            ulonglong2 a45 = *(const ulonglong2*)(ar + 2 * (ty * 8) + 8);
            ulonglong2 a67 = *(const ulonglong2*)(ar + 2 * (ty * 8) + 12);
            ulonglong2 q0  = *(const ulonglong2*)(br + tx * 4);
            unsigned long long av[8] = {a01.x, a01.y, a23.x, a23.y,
                                        a45.x, a45.y, a67.x, a67.y};
            unsigned long long bv[2] = {q0.x, q0.y};
#pragma unroll
            for (int i = 0; i < 8; i++) {
                FMA2(acc[i][0], av[i], bv[0]);
                FMA2(acc[i][1], av[i], bv[1]);
            }
        }
        if (more) {
            int nxt = cur ^ 1;
            *(float2*)&Asd[nxt][acol + 0][2 * arow] = make_float2(aN.x, aN.x);
            *(float2*)&Asd[nxt][acol + 1][2 * arow] = make_float2(aN.y, aN.y);
            *(float2*)&Asd[nxt][acol + 2][2 * arow] = make_float2(aN.z, aN.z);
            *(float2*)&Asd[nxt][acol + 3][2 * arow] = make_float2(aN.w, aN.w);
            *(float2*)&Bs[nxt][brow][bcol] = bN;
        }
        __syncthreads();
        cur ^= 1;
    }

    float bvv[4] = {0, 0, 0, 0};
    if (bias) {
        const float* bp = bias + (long long)bh * biasO;
#pragma unroll
        for (int j = 0; j < 4; j++) bvv[j] = bp[n0 + tx * 4 + j];
    }
#pragma unroll
    for (int i = 0; i < 8; i++) {
        int row = m0 + ty * 8 + i;
        float4 v;
        v.x = lo32(acc[i][0]) + bvv[0];
        v.y = hi32(acc[i][0]) + bvv[1];
        v.z = lo32(acc[i][1]) + bvv[2];
        v.w = hi32(acc[i][1]) + bvv[3];
        *(float4*)&Cb[(long long)row * ldc + n0 + tx * 4] = v;
    }
}

// ============================================================================
// Batched SGEMM, TN (C = alpha * A^T @ B), A is KxM row-major, B is KxN.
// 64x64 tile, BK=16, 256 threads, 4x4 microtile. (Gram matrices only.)
// ============================================================================
__global__ __launch_bounds__(256)
void gemm_tn_64(const float* __restrict__ A, long long aO,
                const float* __restrict__ B, long long bO,
                float* __restrict__ C, long long cO, int ldc,
                int M, int N, int K, float alpha)
{
    int b = blockIdx.z;
    const float* Ab = A + (long long)b * aO;
    const float* Bb = B + (long long)b * bO;
    float*       Cb = C + (long long)b * cO;

    __shared__ __align__(16) float As[16][64];
    __shared__ __align__(16) float Bs[16][64];

    int tid = threadIdx.x;
    int m0 = blockIdx.y * 64;
    int n0 = blockIdx.x * 64;

    int lrow = tid >> 4;
    int lcol = (tid & 15) * 4;
    int tx = tid & 15;
    int ty = tid >> 4;

    const float* Ap = Ab + (long long)lrow * M + m0 + lcol;
    const float* Bp = Bb + (long long)lrow * N + n0 + lcol;

    float acc[4][4];
#pragma unroll
    for (int i = 0; i < 4; i++)
#pragma unroll
        for (int j = 0; j < 4; j++) acc[i][j] = 0.f;

    for (int k0 = 0; k0 < K; k0 += 16) {
        *(float4*)&As[lrow][lcol] = *(const float4*)(Ap + (long long)k0 * M);
        *(float4*)&Bs[lrow][lcol] = *(const float4*)(Bp + (long long)k0 * N);
        __syncthreads();
#pragma unroll
        for (int kk = 0; kk < 16; kk++) {
            float4 a = *(const float4*)&As[kk][ty * 4];
            float4 bb4 = *(const float4*)&Bs[kk][tx * 4];
            float a4[4] = {a.x, a.y, a.z, a.w};
            float b4[4] = {bb4.x, bb4.y, bb4.z, bb4.w};
#pragma unroll
            for (int i = 0; i < 4; i++)
#pragma unroll
                for (int j = 0; j < 4; j++)
                    acc[i][j] = fmaf(a4[i], b4[j], acc[i][j]);
        }
        __syncthreads();
    }

#pragma unroll
    for (int i = 0; i < 4; i++) {
        int row = m0 + ty * 4 + i;
        float4 v;
        v.x = acc[i][0] * alpha;
        v.y = acc[i][1] * alpha;
        v.z = acc[i][2] * alpha;
        v.w = acc[i][3] * alpha;
        *(float4*)&Cb[(long long)row * ldc + n0 + tx * 4] = v;
    }
}

// ============================================================================
// Batched vec @ mat with in-block K-split (4 slices x 64 cols per block).
// out[b] = vec[b] @ mat[b'] (+ add[b]).  grid = (ceil(N/64), nbatch).
// ============================================================================
__global__ __launch_bounds__(256)
void vecmat2(const float* __restrict__ vec, long long vecStride,
             const float* __restrict__ mat, long long matO, long long matI, int bshift,
             const float* __restrict__ add, long long addStride,
             float* __restrict__ out, long long outStride,
             int K, int N)
{
    int b = blockIdx.y;
    int c = (threadIdx.x & 63) + blockIdx.x * 64;
    int s = threadIdx.x >> 6;   // 0..3
    const float* v = vec + (long long)b * vecStride;
    const float* m = mat + (long long)(b >> bshift) * matO
                         + (long long)(b & ((1 << bshift) - 1)) * matI;
    int kpart = K >> 2;
    int kb = s * kpart;
    float acc = 0.f;
    if (c < N)
        for (int k = 0; k < kpart; k++)
            acc = fmaf(v[kb + k], m[(long long)(kb + k) * N + c], acc);

    __shared__ float red[256];
    red[threadIdx.x] = acc;
    __syncthreads();
    if (s == 0 && c < N) {
        float t = red[threadIdx.x] + red[threadIdx.x + 64]
                + red[threadIdx.x + 128] + red[threadIdx.x + 192];
        if (add) t += add[(long long)b * addStride + c];
        out[(long long)b * outStride + c] = t;
    }
}

// ============================================================================
// Launch sequence. Fully-folded math (no softmax => associate freely):
//   S1 = (K1^T V1)/sqrt(A1);  W1 = [Wq1_q S1]_cat @ Wo1;  b1 = [bq1_q S1]_cat @ Wo1 + bo1
//   o1 = x@W1 + b1  (NEVER materialized):
//   K2 = x@(W1 Wk2) + (b1 Wk2 + bk2); V2 likewise
//   S2 = (K2^T V2)/sqrt(A2);  W2 = [Wq2_q S2]_cat @ Wo2;  b2 = [bq2_q S2]_cat @ Wo2 + bo2
//   out = x @ (W1 W2 Wo) + (b1 @ (W2 Wo) + b2 @ Wo + bo)
// ============================================================================
extern "C" void kernel_launch(void* const* d_in, const int* in_sizes, int n_in,
                              void* d_out, int out_size)
{
    (void)in_sizes; (void)n_in; (void)out_size;

    const float* x   = (const float*)d_in[0];
    const float* Wq1 = (const float*)d_in[1];
    const float* bq1 = (const float*)d_in[2];
    const float* Wk1 = (const float*)d_in[3];
    const float* bk1 = (const float*)d_in[4];
    const float* Wv1 = (const float*)d_in[5];
    const float* bv1 = (const float*)d_in[6];
    const float* Wo1 = (const float*)d_in[7];
    const float* bo1 = (const float*)d_in[8];
    const float* Wq2 = (const float*)d_in[9];
    const float* bq2 = (const float*)d_in[10];
    const float* Wk2 = (const float*)d_in[11];
    const float* bk2 = (const float*)d_in[12];
    const float* Wv2 = (const float*)d_in[13];
    const float* bv2 = (const float*)d_in[14];
    const float* Wo2 = (const float*)d_in[15];
    const float* bo2 = (const float*)d_in[16];
    const float* Wo  = (const float*)d_in[17];
    const float* bo  = (const float*)d_in[18];
    float* out = (float*)d_out;

    float *K1, *V1, *S1, *P1, *bP1, *W1, *b1;
    float *Wk2e, *Wv2e, *bk2e, *bv2e, *K2, *V2, *S2, *bP2, *P2, *b2;
    float *W2, *W23, *Wf, *b3, *bf;
    cudaGetSymbolAddress((void**)&K1,   g_K1);
    cudaGetSymbolAddress((void**)&V1,   g_V1);
    cudaGetSymbolAddress((void**)&S1,   g_S1);
    cudaGetSymbolAddress((void**)&P1,   g_P1);
    cudaGetSymbolAddress((void**)&bP1,  g_bP1);
    cudaGetSymbolAddress((void**)&W1,   g_W1);
    cudaGetSymbolAddress((void**)&b1,   g_b1);
    cudaGetSymbolAddress((void**)&Wk2e, g_Wk2e);
    cudaGetSymbolAddress((void**)&Wv2e, g_Wv2e);
    cudaGetSymbolAddress((void**)&bk2e, g_bk2e);
    cudaGetSymbolAddress((void**)&bv2e, g_bv2e);
    cudaGetSymbolAddress((void**)&K2,   g_K2);
    cudaGetSymbolAddress((void**)&V2,   g_V2);
    cudaGetSymbolAddress((void**)&S2,   g_S2);
    cudaGetSymbolAddress((void**)&bP2,  g_bP2);
    cudaGetSymbolAddress((void**)&P2,   g_P2);
    cudaGetSymbolAddress((void**)&b2,   g_b2);
    cudaGetSymbolAddress((void**)&W2,   g_W2);
    cudaGetSymbolAddress((void**)&W23,  g_W23);
    cudaGetSymbolAddress((void**)&Wf,   g_Wf);
    cudaGetSymbolAddress((void**)&b3,   g_b3);
    cudaGetSymbolAddress((void**)&bf,   g_bf);

    const float inv_sa1 = 0.08838834764831845f;  // 1/sqrt(128)
    const float inv_sa2 = 0.125f;                // 1/sqrt(64)

    // -------- tier 1 --------
    // K1[g] = x @ Wk1[g] + bk1[g]   [2048,128], K=512
    gemm128p<<<dim3(1, 16, 8), 256>>>(x, 0, 0, Wk1, (long long)DDIM*AD1, 0,
                                      bk1, AD1, K1, (long long)NTOK*AD1, 0, AD1,
                                      AD1, DDIM, 0);
    // V1[g]
    gemm128p<<<dim3(1, 16, 8), 256>>>(x, 0, 0, Wv1, (long long)DDIM*AD1, 0,
                                      bv1, AD1, V1, (long long)NTOK*AD1, 0, AD1,
                                      AD1, DDIM, 0);
    // S1[g] = K1^T V1 / sqrt(A1)    [128,128]
    gemm_tn_64<<<dim3(2, 2, 8), 256>>>(K1, (long long)NTOK*AD1,
                                       V1, (long long)NTOK*AD1,
                                       S1, (long long)AD1*AD1, AD1,
                                       AD1, AD1, NTOK, inv_sa1);
    // bP1[g, q*A1:..] = bq1[g,q] @ S1[g]
    vecmat2<<<dim3(2, 64), 256>>>(bq1, AD1, S1, (long long)AD1*AD1, 0, 3,
                                  (const float*)nullptr, 0, bP1, AD1, AD1, AD1);
    // P1cat[g][:, q*A1:..] = Wq1[g,q] @ S1[g]   [512,128]x64
    gemm128p<<<dim3(1, 4, 64), 256>>>(Wq1, (long long)NQH*DDIM*AD1, (long long)DDIM*AD1,
                                      S1, (long long)AD1*AD1, 0,
                                      (const float*)nullptr, 0,
                                      P1, (long long)DDIM*NQH*AD1, AD1, NQH*AD1,
                                      AD1, AD1, 3);
    // b1[g] = bP1[g] @ Wo1[g] + bo1[g]
    vecmat2<<<dim3(8, 8), 256>>>(bP1, NQH*AD1, Wo1, (long long)NQH*AD1*DDIM, 0, 0,
                                 bo1, DDIM, b1, DDIM, NQH*AD1, DDIM);
    // W1[g] = P1cat[g] @ Wo1[g]   [512,512], K=1024
    gemm128p<<<dim3(4, 4, 8), 256>>>(P1, (long long)DDIM*NQH*AD1, 0,
                                     Wo1, (long long)NQH*AD1*DDIM, 0,
                                     (const float*)nullptr, 0,
                                     W1, (long long)DDIM*DDIM, 0, DDIM,
                                     DDIM, NQH*AD1, 0);

    // -------- tier 2 (o1 folded away) --------
    // Wk2e[g] = W1[g] @ Wk2[g]   [512,64], K=512
    gemm64w<<<dim3(1, 4, 8), 256>>>(W1, (long long)DDIM*DDIM, 0,
                                    Wk2, (long long)DDIM*AD2, 0,
                                    (const float*)nullptr, 0,
                                    Wk2e, (long long)DDIM*AD2, 0, AD2,
                                    AD2, DDIM, 0);
    gemm64w<<<dim3(1, 4, 8), 256>>>(W1, (long long)DDIM*DDIM, 0,
                                    Wv2, (long long)DDIM*AD2, 0,
                                    (const float*)nullptr, 0,
                                    Wv2e, (long long)DDIM*AD2, 0, AD2,
                                    AD2, DDIM, 0);
    // bk2e[g] = b1[g] @ Wk2[g] + bk2[g]
    vecmat2<<<dim3(1, 8), 256>>>(b1, DDIM, Wk2, (long long)DDIM*AD2, 0, 0,
                                 bk2, AD2, bk2e, AD2, DDIM, AD2);
    vecmat2<<<dim3(1, 8), 256>>>(b1, DDIM, Wv2, (long long)DDIM*AD2, 0, 0,
                                 bv2, AD2, bv2e, AD2, DDIM, AD2);
    // K2[g] = x @ Wk2e[g] + bk2e[g]   [2048,64], K=512
    gemm64w<<<dim3(1, 16, 8), 256>>>(x, 0, 0, Wk2e, (long long)DDIM*AD2, 0,
                                     bk2e, AD2, K2, (long long)NTOK*AD2, 0, AD2,
                                     AD2, DDIM, 0);
    gemm64w<<<dim3(1, 16, 8), 256>>>(x, 0, 0, Wv2e, (long long)DDIM*AD2, 0,
                                     bv2e, AD2, V2, (long long)NTOK*AD2, 0, AD2,
                                     AD2, DDIM, 0);
    // S2[g] = K2^T V2 / sqrt(A2)   [64,64]
    gemm_tn_64<<<dim3(1, 1, 8), 256>>>(K2, (long long)NTOK*AD2,
                                       V2, (long long)NTOK*AD2,
                                       S2, (long long)AD2*AD2, AD2,
                                       AD2, AD2, NTOK, inv_sa2);
    // bP2, P2
    vecmat2<<<dim3(1, 64), 256>>>(bq2, AD2, S2, (long long)AD2*AD2, 0, 3,
                                  (const float*)nullptr, 0, bP2, AD2, AD2, AD2);
    gemm64w<<<dim3(1, 4, 64), 256>>>(Wq2, (long long)NQH*DDIM*AD2, (long long)DDIM*AD2,
                                     S2, (long long)AD2*AD2, 0,
                                     (const float*)nullptr, 0,
                                     P2, (long long)DDIM*NQH*AD2, AD2, NQH*AD2,
                                     AD2, AD2, 3);
    // b2[g] = bP2[g] @ Wo2[g] + bo2[g]
    vecmat2<<<dim3(8, 8), 256>>>(bP2, NQH*AD2, Wo2, (long long)NQH*AD2*DDIM, 0, 0,
                                 bo2, DDIM, b2, DDIM, NQH*AD2, DDIM);
    // W2[g] = P2cat[g] @ Wo2[g]   [512,512], K=512
    gemm128p<<<dim3(4, 4, 8), 256>>>(P2, (long long)DDIM*NQH*AD2, 0,
                                     Wo2, (long long)NQH*AD2*DDIM, 0,
                                     (const float*)nullptr, 0,
                                     W2, (long long)DDIM*DDIM, 0, DDIM,
                                     DDIM, NQH*AD2, 0);
    // W23[g] = W2[g] @ Wo
    gemm128p<<<dim3(4, 4, 8), 256>>>(W2, (long long)DDIM*DDIM, 0,
                                     Wo, 0, 0,
                                     (const float*)nullptr, 0,
                                     W23, (long long)DDIM*DDIM, 0, DDIM,
                                     DDIM, DDIM, 0);
    // b3[g] = b2[g] @ Wo + bo
    vecmat2<<<dim3(8, 8), 256>>>(b2, DDIM, Wo, 0, 0, 0,
                                 bo, 0, b3, DDIM, DDIM, DDIM);
    // bf[g] = b1[g] @ W23[g] + b3[g]
    vecmat2<<<dim3(8, 8), 256>>>(b1, DDIM, W23, (long long)DDIM*DDIM, 0, 0,
                                 b3, DDIM, bf, DDIM, DDIM, DDIM);
    // Wf[g] = W1[g] @ W23[g]
    gemm128p<<<dim3(4, 4, 8), 256>>>(W1, (long long)DDIM*DDIM, 0,
                                     W23, (long long)DDIM*DDIM, 0,
                                     (const float*)nullptr, 0,
                                     Wf, (long long)DDIM*DDIM, 0, DDIM,
                                     DDIM, DDIM, 0);
    // out[g] = x @ Wf[g] + bf[g]   [2048,512] -> rows [g*2048,(g+1)*2048)
    gemm128p<<<dim3(4, 16, 8), 256>>>(x, 0, 0,
                                      Wf, (long long)DDIM*DDIM, 0,
                                      bf, DDIM,
                                      out, (long long)NTOK*DDIM, 0, DDIM,
                                      DDIM, DDIM, 0);
}

// round 3
// speedup vs baseline: 1.8571x; 1.5332x over previous
#include <cuda_runtime.h>
#include <stdint.h>

// ---- problem constants ----
#define NTOK 2048
#define DDIM 512
#define GRP  8
#define NQH  8
#define AD1  128
#define AD2  64

// ---- scratch (device globals: allocation-free) ----
__device__ float g_K1[GRP*NTOK*AD1];
__device__ float g_V1[GRP*NTOK*AD1];
__device__ float g_Sp[GRP*8*AD1*AD1];   // split-K partials (4MB, reused)
__device__ float g_S1[GRP*AD1*AD1];
__device__ float g_P1[GRP*DDIM*NQH*AD1];
__device__ float g_bP1[GRP*NQH*AD1];
__device__ float g_W1[GRP*DDIM*DDIM];
__device__ float g_b1[GRP*DDIM];
__device__ float g_Wk2e[GRP*DDIM*AD2];
__device__ float g_Wv2e[GRP*DDIM*AD2];
__device__ float g_bk2e[GRP*AD2];
__device__ float g_bv2e[GRP*AD2];
__device__ float g_K2[GRP*NTOK*AD2];
__device__ float g_V2[GRP*NTOK*AD2];
__device__ float g_S2[GRP*AD2*AD2];
__device__ float g_bP2[GRP*NQH*AD2];
__device__ float g_P2[GRP*DDIM*NQH*AD2];
__device__ float g_b2[GRP*DDIM];
__device__ float g_W2[GRP*DDIM*DDIM];
__device__ float g_W23[GRP*DDIM*DDIM];
__device__ float g_Wf[GRP*DDIM*DDIM];
__device__ float g_b3[GRP*DDIM];
__device__ float g_bf[GRP*DDIM];

__device__ __forceinline__ float lo32(unsigned long long v) {
    return __uint_as_float((unsigned)(v & 0xffffffffULL));
}
__device__ __forceinline__ float hi32(unsigned long long v) {
    return __uint_as_float((unsigned)(v >> 32));
}
__device__ __forceinline__ unsigned long long pack2(float s) {
    unsigned long long d;
    unsigned u = __float_as_uint(s);
    asm("mov.b64 %0, {%1, %1};" : "=l"(d) : "r"(u));
    return d;
}
#define FMA2(acc, a, b) \
    asm("fma.rn.f32x2 %0, %1, %2, %0;" : "+l"(acc) : "l"(a), "l"(b))

// ============================================================================
// Packed-fp32x2 batched SGEMM, NN, 128x128 tile, BK=8, 256 threads,
// 8x8 microtile, double-buffered smem, NON-duplicated A (broadcast LDS) with
// register packing on the ALU pipe. Optional second output set selected by
// blockIdx.z >= zsplit (for fusing two independent GEMMs sharing A).
// ============================================================================
__global__ __launch_bounds__(256)
void gemm128p2(const float* __restrict__ A, long long aO, long long aI,
               const float* __restrict__ B, const float* __restrict__ bias,
               float* __restrict__ C,
               const float* __restrict__ B2, const float* __restrict__ bias2,
               float* __restrict__ C2, int zsplit,
               long long bO, long long bI, long long biasO,
               long long cO, long long cI, int ldc,
               int N, int K, int bshift)
{
    int z = blockIdx.z;
    const float* Bu = B; const float* biasu = bias; float* Cu = C;
    if (z >= zsplit) { z -= zsplit; Bu = B2; biasu = bias2; Cu = C2; }
    int bh = z >> bshift;
    int bl = z & ((1 << bshift) - 1);
    const float* Ab = A + (long long)bh * aO + (long long)bl * aI;
    const float* Bb = Bu + (long long)bh * bO + (long long)bl * bI;
    float*       Cb = Cu + (long long)bh * cO + (long long)bl * cI;

    __shared__ __align__(16) float As[2][8][132];  // padded rows (bank spread)
    __shared__ __align__(16) float Bs[2][8][128];

    int tid = threadIdx.x;
    int m0 = blockIdx.y * 128;
    int n0 = blockIdx.x * 128;

    int arow = tid >> 1;         // 0..127
    int acol = (tid & 1) * 4;    // 0 or 4
    int brow = tid >> 5;         // 0..7
    int bcol = (tid & 31) * 4;   // 0..124
    int tx = tid & 15;
    int ty = tid >> 4;

    const float* Ap = Ab + (long long)(m0 + arow) * K + acol;
    const float* Bp = Bb + (long long)brow * N + n0 + bcol;

    unsigned long long acc[8][4];
#pragma unroll
    for (int i = 0; i < 8; i++)
#pragma unroll
        for (int j = 0; j < 4; j++) acc[i][j] = 0ULL;

    {   // prologue
        float4 a4 = *(const float4*)Ap;
        float4 b4 = *(const float4*)Bp;
        As[0][acol + 0][arow] = a4.x;
        As[0][acol + 1][arow] = a4.y;
        As[0][acol + 2][arow] = a4.z;
        As[0][acol + 3][arow] = a4.w;
        *(float4*)&Bs[0][brow][bcol] = b4;
    }
    __syncthreads();

    int cur = 0;
    for (int k0 = 0; k0 < K; k0 += 8) {
        bool more = (k0 + 8) < K;
        float4 aN, bN;
        if (more) {
            aN = *(const float4*)(Ap + k0 + 8);
            bN = *(const float4*)(Bp + (long long)(k0 + 8) * N);
        }
#pragma unroll
        for (int kk = 0; kk < 8; kk++) {
            const float* ar = &As[cur][kk][0];
            const float* br = &Bs[cur][kk][0];
            float4 aA = *(const float4*)(ar + ty * 4);
            float4 aB = *(const float4*)(ar + 64 + ty * 4);
            ulonglong2 q0 = *(const ulonglong2*)(br + tx * 4);
            ulonglong2 q1 = *(const ulonglong2*)(br + 64 + tx * 4);
            unsigned long long ap[8];
            ap[0] = pack2(aA.x); ap[1] = pack2(aA.y);
            ap[2] = pack2(aA.z); ap[3] = pack2(aA.w);
            ap[4] = pack2(aB.x); ap[5] = pack2(aB.y);
            ap[6] = pack2(aB.z); ap[7] = pack2(aB.w);
            unsigned long long bv[4] = {q0.x, q0.y, q1.x, q1.y};
#pragma unroll
            for (int i = 0; i < 8; i++)
#pragma unroll
                for (int j = 0; j < 4; j++)
                    FMA2(acc[i][j], ap[i], bv[j]);
        }
        if (more) {
            int nxt = cur ^ 1;
            As[nxt][acol + 0][arow] = aN.x;
            As[nxt][acol + 1][arow] = aN.y;
            As[nxt][acol + 2][arow] = aN.z;
            As[nxt][acol + 3][arow] = aN.w;
            *(float4*)&Bs[nxt][brow][bcol] = bN;
        }
        __syncthreads();
        cur ^= 1;
    }

    float bvv[8] = {0, 0, 0, 0, 0, 0, 0, 0};
    if (biasu) {
        const float* bp = biasu + (long long)bh * biasO;
#pragma unroll
        for (int j = 0; j < 4; j++) {
            bvv[j]     = bp[n0 + tx * 4 + j];
            bvv[4 + j] = bp[n0 + 64 + tx * 4 + j];
        }
    }
#pragma unroll
    for (int i = 0; i < 8; i++) {
        int row = m0 + ((i < 4) ? (ty * 4 + i) : (64 + ty * 4 + (i - 4)));
        float4 v0, v1;
        v0.x = lo32(acc[i][0]) + bvv[0];
        v0.y = hi32(acc[i][0]) + bvv[1];
        v0.z = lo32(acc[i][1]) + bvv[2];
        v0.w = hi32(acc[i][1]) + bvv[3];
        v1.x = lo32(acc[i][2]) + bvv[4];
        v1.y = hi32(acc[i][2]) + bvv[5];
        v1.z = lo32(acc[i][3]) + bvv[6];
        v1.w = hi32(acc[i][3]) + bvv[7];
        *(float4*)&Cb[(long long)row * ldc + n0 + tx * 4]      = v0;
        *(float4*)&Cb[(long long)row * ldc + n0 + 64 + tx * 4] = v1;
    }
}

// ============================================================================
// Same scheme, 128x64 tile, 8x4 microtile (for N=64 outputs). Dual-set capable.
// ============================================================================
__global__ __launch_bounds__(256)
void gemm64w2(const float* __restrict__ A, long long aO, long long aI,
              const float* __restrict__ B, const float* __restrict__ bias,
              float* __restrict__ C,
              const float* __restrict__ B2, const float* __restrict__ bias2,
              float* __restrict__ C2, int zsplit,
              long long bO, long long bI, long long biasO,
              long long cO, long long cI, int ldc,
              int N, int K, int bshift)
{
    int z = blockIdx.z;
    const float* Bu = B; const float* biasu = bias; float* Cu = C;
    if (z >= zsplit) { z -= zsplit; Bu = B2; biasu = bias2; Cu = C2; }
    int bh = z >> bshift;
    int bl = z & ((1 << bshift) - 1);
    const float* Ab = A + (long long)bh * aO + (long long)bl * aI;
    const float* Bb = Bu + (long long)bh * bO + (long long)bl * bI;
    float*       Cb = Cu + (long long)bh * cO + (long long)bl * cI;

    __shared__ __align__(16) float As[2][8][132];
    __shared__ __align__(16) float Bs[2][8][64];

    int tid = threadIdx.x;
    int m0 = blockIdx.y * 128;
    int n0 = blockIdx.x * 64;

    int arow = tid >> 1;         // 0..127
    int acol = (tid & 1) * 4;
    int brow = tid >> 5;         // 0..7
    int bcol = (tid & 31) * 2;   // 0..62
    int tx = tid & 15;
    int ty = tid >> 4;           // rows ty*8..ty*8+7

    const float* Ap = Ab + (long long)(m0 + arow) * K + acol;
    const float* Bp = Bb + (long long)brow * N + n0 + bcol;

    unsigned long long acc[8][2];
#pragma unroll
    for (int i = 0; i < 8; i++) { acc[i][0] = 0ULL; acc[i][1] = 0ULL; }

    {
        float4 a4 = *(const float4*)Ap;
        float2 b2 = *(const float2*)Bp;
        As[0][acol + 0][arow] = a4.x;
        As[0][acol + 1][arow] = a4.y;
        As[0][acol + 2][arow] = a4.z;
        As[0][acol + 3][arow] = a4.w;
        *(float2*)&Bs[0][brow][bcol] = b2;
    }
    __syncthreads();

    int cur = 0;
    for (int k0 = 0; k0 < K; k0 += 8) {
        bool more = (k0 + 8) < K;
        float4 aN; float2 bN;
        if (more) {
            aN = *(const float4*)(Ap + k0 + 8);
            bN = *(const float2*)(Bp + (long long)(k0 + 8) * N);
        }
#pragma unroll
        for (int kk = 0; kk < 8; kk++) {
            const float* ar = &As[cur][kk][0];
            const float* br = &Bs[cur][kk][0];
            float4 aA = *(const float4*)(ar + ty * 8);
            float4 aB = *(const float4*)(ar + ty * 8 + 4);
            ulonglong2 q0 = *(const ulonglong2*)(br + tx * 4);
            unsigned long long ap[8];
            ap[0] = pack2(aA.x); ap[1] = pack2(aA.y);
            ap[2] = pack2(aA.z); ap[3] = pack2(aA.w);
            ap[4] = pack2(aB.x); ap[5] = pack2(aB.y);
            ap[6] = pack2(aB.z); ap[7] = pack2(aB.w);
#pragma unroll
            for (int i = 0; i < 8; i++) {
                FMA2(acc[i][0], ap[i], q0.x);
                FMA2(acc[i][1], ap[i], q0.y);
            }
        }
        if (more) {
            int nxt = cur ^ 1;
            As[nxt][acol + 0][arow] = aN.x;
            As[nxt][acol + 1][arow] = aN.y;
            As[nxt][acol + 2][arow] = aN.z;
            As[nxt][acol + 3][arow] = aN.w;
            *(float2*)&Bs[nxt][brow][bcol] = bN;
        }
        __syncthreads();
        cur ^= 1;
    }

    float bvv[4] = {0, 0, 0, 0};
    if (biasu) {
        const float* bp = biasu + (long long)bh * biasO;
#pragma unroll
        for (int j = 0; j < 4; j++) bvv[j] = bp[n0 + tx * 4 + j];
    }
#pragma unroll
    for (int i = 0; i < 8; i++) {
        int row = m0 + ty * 8 + i;
        float4 v;
        v.x = lo32(acc[i][0]) + bvv[0];
        v.y = hi32(acc[i][0]) + bvv[1];
        v.z = lo32(acc[i][1]) + bvv[2];
        v.w = hi32(acc[i][1]) + bvv[3];
        *(float4*)&Cb[(long long)row * ldc + n0 + tx * 4] = v;
    }
}

// ============================================================================
// Split-K TN GEMM partials: Cp[z] = A[g][kslice]^T @ B[g][kslice].
// z = g*8 + chunk; A,B are [Ktot x {M,N}] row-major per batch.
// 64x64 tile, BK=16, 4x4 microtile.
// ============================================================================
__global__ __launch_bounds__(256)
void gemm_tn_sk(const float* __restrict__ A, long long aO,
                const float* __restrict__ B, long long bO,
                float* __restrict__ Cp, int M, int N, int Ktot)
{
    int z = blockIdx.z;
    int g = z >> 3, c = z & 7;
    int kl = Ktot >> 3;
    const float* Ab = A + (long long)g * aO + (long long)c * kl * M;
    const float* Bb = B + (long long)g * bO + (long long)c * kl * N;
    float*       Cb = Cp + (long long)z * M * N;

    __shared__ __align__(16) float As[16][64];
    __shared__ __align__(16) float Bs[16][64];

    int tid = threadIdx.x;
    int m0 = blockIdx.y * 64;
    int n0 = blockIdx.x * 64;

    int lrow = tid >> 4;
    int lcol = (tid & 15) * 4;
    int tx = tid & 15;
    int ty = tid >> 4;

    const float* Ap = Ab + (long long)lrow * M + m0 + lcol;
    const float* Bp = Bb + (long long)lrow * N + n0 + lcol;

    float acc[4][4];
#pragma unroll
    for (int i = 0; i < 4; i++)
#pragma unroll
        for (int j = 0; j < 4; j++) acc[i][j] = 0.f;

    for (int k0 = 0; k0 < kl; k0 += 16) {
        *(float4*)&As[lrow][lcol] = *(const float4*)(Ap + (long long)k0 * M);
        *(float4*)&Bs[lrow][lcol] = *(const float4*)(Bp + (long long)k0 * N);
        __syncthreads();
#pragma unroll
        for (int kk = 0; kk < 16; kk++) {
            float4 a = *(const float4*)&As[kk][ty * 4];
            float4 bb4 = *(const float4*)&Bs[kk][tx * 4];
            float a4[4] = {a.x, a.y, a.z, a.w};
            float b4[4] = {bb4.x, bb4.y, bb4.z, bb4.w};
#pragma unroll
            for (int i = 0; i < 4; i++)
#pragma unroll
                for (int j = 0; j < 4; j++)
                    acc[i][j] = fmaf(a4[i], b4[j], acc[i][j]);
        }
        __syncthreads();
    }

#pragma unroll
    for (int i = 0; i < 4; i++) {
        int row = m0 + ty * 4 + i;
        float4 v = {acc[i][0], acc[i][1], acc[i][2], acc[i][3]};
        *(float4*)&Cb[(long long)row * N + n0 + tx * 4] = v;
    }
}

// C[g] = alpha * sum_{c=0..7} Cp[g*8+c]
__global__ void reduce8(const float* __restrict__ Cp, float* __restrict__ C,
                        float alpha, int MN)
{
    int i = blockIdx.x * 256 + threadIdx.x;
    int g = blockIdx.y;
    const float* p = Cp + (long long)g * 8 * MN + i;
    float s = 0.f;
#pragma unroll
    for (int c = 0; c < 8; c++) s += p[(long long)c * MN];
    C[(long long)g * MN + i] = alpha * s;
}

// ============================================================================
// Batched vec @ mat with in-block K-split; dual-set via blockIdx.y >= ysplit.
// ============================================================================
__global__ __launch_bounds__(256)
void vecmat2(const float* __restrict__ vec, long long vecStride,
             const float* __restrict__ mat, long long matO, long long matI, int bshift,
             const float* __restrict__ add, long long addStride,
             float* __restrict__ out, long long outStride,
             const float* __restrict__ vec2, const float* __restrict__ mat2,
             const float* __restrict__ add2, float* __restrict__ out2,
             int ysplit, int K, int N)
{
    int b = blockIdx.y;
    const float* vecu = vec; const float* matu = mat;
    const float* addu = add; float* outu = out;
    if (b >= ysplit) { b -= ysplit; vecu = vec2; matu = mat2; addu = add2; outu = out2; }
    int c = (threadIdx.x & 63) + blockIdx.x * 64;
    int s = threadIdx.x >> 6;   // 0..3
    const float* v = vecu + (long long)b * vecStride;
    const float* m = matu + (long long)(b >> bshift) * matO
                          + (long long)(b & ((1 << bshift) - 1)) * matI;
    int kpart = K >> 2;
    int kb = s * kpart;
    float acc = 0.f;
    if (c < N)
        for (int k = 0; k < kpart; k++)
            acc = fmaf(v[kb + k], m[(long long)(kb + k) * N + c], acc);

    __shared__ float red[256];
    red[threadIdx.x] = acc;
    __syncthreads();
    if (s == 0 && c < N) {
        float t = red[threadIdx.x] + red[threadIdx.x + 64]
                + red[threadIdx.x + 128] + red[threadIdx.x + 192];
        if (addu) t += addu[(long long)b * addStride + c];
        outu[(long long)b * outStride + c] = t;
    }
}

#define NOSET2 (const float*)nullptr, (const float*)nullptr, (float*)nullptr, (1<<30)

extern "C" void kernel_launch(void* const* d_in, const int* in_sizes, int n_in,
                              void* d_out, int out_size)
{
    (void)in_sizes; (void)n_in; (void)out_size;

    const float* x   = (const float*)d_in[0];
    const float* Wq1 = (const float*)d_in[1];
    const float* bq1 = (const float*)d_in[2];
    const float* Wk1 = (const float*)d_in[3];
    const float* bk1 = (const float*)d_in[4];
    const float* Wv1 = (const float*)d_in[5];
    const float* bv1 = (const float*)d_in[6];
    const float* Wo1 = (const float*)d_in[7];
    const float* bo1 = (const float*)d_in[8];
    const float* Wq2 = (const float*)d_in[9];
    const float* bq2 = (const float*)d_in[10];
    const float* Wk2 = (const float*)d_in[11];
    const float* bk2 = (const float*)d_in[12];
    const float* Wv2 = (const float*)d_in[13];
    const float* bv2 = (const float*)d_in[14];
    const float* Wo2 = (const float*)d_in[15];
    const float* bo2 = (const float*)d_in[16];
    const float* Wo  = (const float*)d_in[17];
    const float* bo  = (const float*)d_in[18];
    float* out = (float*)d_out;

    float *K1, *V1, *Sp, *S1, *P1, *bP1, *W1, *b1;
    float *Wk2e, *Wv2e, *bk2e, *bv2e, *K2, *V2, *S2, *bP2, *P2, *b2;
    float *W2, *W23, *Wf, *b3, *bf;
    cudaGetSymbolAddress((void**)&K1,   g_K1);
    cudaGetSymbolAddress((void**)&V1,   g_V1);
    cudaGetSymbolAddress((void**)&Sp,   g_Sp);
    cudaGetSymbolAddress((void**)&S1,   g_S1);
    cudaGetSymbolAddress((void**)&P1,   g_P1);
    cudaGetSymbolAddress((void**)&bP1,  g_bP1);
    cudaGetSymbolAddress((void**)&W1,   g_W1);
    cudaGetSymbolAddress((void**)&b1,   g_b1);
    cudaGetSymbolAddress((void**)&Wk2e, g_Wk2e);
    cudaGetSymbolAddress((void**)&Wv2e, g_Wv2e);
    cudaGetSymbolAddress((void**)&bk2e, g_bk2e);
    cudaGetSymbolAddress((void**)&bv2e, g_bv2e);
    cudaGetSymbolAddress((void**)&K2,   g_K2);
    cudaGetSymbolAddress((void**)&V2,   g_V2);
    cudaGetSymbolAddress((void**)&S2,   g_S2);
    cudaGetSymbolAddress((void**)&bP2,  g_bP2);
    cudaGetSymbolAddress((void**)&P2,   g_P2);
    cudaGetSymbolAddress((void**)&b2,   g_b2);
    cudaGetSymbolAddress((void**)&W2,   g_W2);
    cudaGetSymbolAddress((void**)&W23,  g_W23);
    cudaGetSymbolAddress((void**)&Wf,   g_Wf);
    cudaGetSymbolAddress((void**)&b3,   g_b3);
    cudaGetSymbolAddress((void**)&bf,   g_bf);

    const float inv_sa1 = 0.08838834764831845f;  // 1/sqrt(128)
    const float inv_sa2 = 0.125f;                // 1/sqrt(64)

    // 1. K1 & V1 fused: [2048,128] = x @ Wk1/Wv1 (+bias), 256 CTAs
    gemm128p2<<<dim3(1, 16, 16), 256>>>(x, 0, 0,
                                        Wk1, bk1, K1, Wv1, bv1, V1, 8,
                                        (long long)DDIM*AD1, 0, AD1,
                                        (long long)NTOK*AD1, 0, AD1,
                                        AD1, DDIM, 0);
    // 2-3. S1 = K1^T V1 / sqrt(A1), split-K x8 + reduce
    gemm_tn_sk<<<dim3(2, 2, 64), 256>>>(K1, (long long)NTOK*AD1,
                                        V1, (long long)NTOK*AD1,
                                        Sp, AD1, AD1, NTOK);
    reduce8<<<dim3(64, 8), 256>>>(Sp, S1, inv_sa1, AD1*AD1);
    // 4. bP1[g,q] = bq1[g,q] @ S1[g]
    vecmat2<<<dim3(2, 64), 256>>>(bq1, AD1, S1, (long long)AD1*AD1, 0, 3,
                                  (const float*)nullptr, 0, bP1, AD1,
                                  nullptr, nullptr, nullptr, nullptr, (1<<30),
                                  AD1, AD1);
    // 5. P1cat = Wq1[g,q] @ S1[g]  [512,128] x64
    gemm128p2<<<dim3(1, 4, 64), 256>>>(Wq1, (long long)NQH*DDIM*AD1, (long long)DDIM*AD1,
                                       S1, (const float*)nullptr, P1, NOSET2,
                                       (long long)AD1*AD1, 0, 0,
                                       (long long)DDIM*NQH*AD1, AD1, NQH*AD1,
                                       AD1, AD1, 3);
    // 6. b1 = bP1 @ Wo1 + bo1
    vecmat2<<<dim3(8, 8), 256>>>(bP1, NQH*AD1, Wo1, (long long)NQH*AD1*DDIM, 0, 0,
                                 bo1, DDIM, b1, DDIM,
                                 nullptr, nullptr, nullptr, nullptr, (1<<30),
                                 NQH*AD1, DDIM);
    // 7. W1 = P1cat @ Wo1   [512,512] K=1024
    gemm128p2<<<dim3(4, 4, 8), 256>>>(P1, (long long)DDIM*NQH*AD1, 0,
                                      Wo1, (const float*)nullptr, W1, NOSET2,
                                      (long long)NQH*AD1*DDIM, 0, 0,
                                      (long long)DDIM*DDIM, 0, DDIM,
                                      DDIM, NQH*AD1, 0);
    // 8. Wk2e & Wv2e fused: W1 @ Wk2 / Wv2  [512,64]
    gemm64w2<<<dim3(1, 4, 16), 256>>>(W1, (long long)DDIM*DDIM, 0,
                                      Wk2, (const float*)nullptr, Wk2e,
                                      Wv2, (const float*)nullptr, Wv2e, 8,
                                      (long long)DDIM*AD2, 0, 0,
                                      (long long)DDIM*AD2, 0, AD2,
                                      AD2, DDIM, 0);
    // 9. bk2e & bv2e fused
    vecmat2<<<dim3(1, 16), 256>>>(b1, DDIM, Wk2, (long long)DDIM*AD2, 0, 0,
                                  bk2, AD2, bk2e, AD2,
                                  b1, Wv2, bv2, bv2e, 8,
                                  DDIM, AD2);
    // 10. K2 & V2 fused: x @ Wk2e/Wv2e + bias  [2048,64]
    gemm64w2<<<dim3(1, 16, 16), 256>>>(x, 0, 0,
                                       Wk2e, bk2e, K2, Wv2e, bv2e, V2, 8,
                                       (long long)DDIM*AD2, 0, AD2,
                                       (long long)NTOK*AD2, 0, AD2,
                                       AD2, DDIM, 0);
    // 11-12. S2 split-K + reduce
    gemm_tn_sk<<<dim3(1, 1, 64), 256>>>(K2, (long long)NTOK*AD2,
                                        V2, (long long)NTOK*AD2,
                                        Sp, AD2, AD2, NTOK);
    reduce8<<<dim3(16, 8), 256>>>(Sp, S2, inv_sa2, AD2*AD2);
    // 13. bP2
    vecmat2<<<dim3(1, 64), 256>>>(bq2, AD2, S2, (long long)AD2*AD2, 0, 3,
                                  (const float*)nullptr, 0, bP2, AD2,
                                  nullptr, nullptr, nullptr, nullptr, (1<<30),
                                  AD2, AD2);
    // 14. P2cat = Wq2[g,q] @ S2[g]  [512,64] x64
    gemm64w2<<<dim3(1, 4, 64), 256>>>(Wq2, (long long)NQH*DDIM*AD2, (long long)DDIM*AD2,
                                      S2, (const float*)nullptr, P2, NOSET2,
                                      (long long)AD2*AD2, 0, 0,
                                      (long long)DDIM*NQH*AD2, AD2, NQH*AD2,
                                      AD2, AD2, 3);
    // 15. b2 = bP2 @ Wo2 + bo2
    vecmat2<<<dim3(8, 8), 256>>>(bP2, NQH*AD2, Wo2, (long long)NQH*AD2*DDIM, 0, 0,
                                 bo2, DDIM, b2, DDIM,
                                 nullptr, nullptr, nullptr, nullptr, (1<<30),
                                 NQH*AD2, DDIM);
    // 16. W2 = P2cat @ Wo2   [512,512] K=512
    gemm128p2<<<dim3(4, 4, 8), 256>>>(P2, (long long)DDIM*NQH*AD2, 0,
                                      Wo2, (const float*)nullptr, W2, NOSET2,
                                      (long long)NQH*AD2*DDIM, 0, 0,
                                      (long long)DDIM*DDIM, 0, DDIM,
                                      DDIM, NQH*AD2, 0);
    // 17. W23 = W2 @ Wo
    gemm128p2<<<dim3(4, 4, 8), 256>>>(W2, (long long)DDIM*DDIM, 0,
                                      Wo, (const float*)nullptr, W23, NOSET2,
                                      0, 0, 0,
                                      (long long)DDIM*DDIM, 0, DDIM,
                                      DDIM, DDIM, 0);
    // 18. b3 = b2 @ Wo + bo
    vecmat2<<<dim3(8, 8), 256>>>(b2, DDIM, Wo, 0, 0, 0,
                                 bo, 0, b3, DDIM,
                                 nullptr, nullptr, nullptr, nullptr, (1<<30),
                                 DDIM, DDIM);
    // 19. bf = b1 @ W23 + b3
    vecmat2<<<dim3(8, 8), 256>>>(b1, DDIM, W23, (long long)DDIM*DDIM, 0, 0,
                                 b3, DDIM, bf, DDIM,
                                 nullptr, nullptr, nullptr, nullptr, (1<<30),
                                 DDIM, DDIM);
    // 20. Wf = W1 @ W23
    gemm128p2<<<dim3(4, 4, 8), 256>>>(W1, (long long)DDIM*DDIM, 0,
                                      W23, (const float*)nullptr, Wf, NOSET2,
                                      (long long)DDIM*DDIM, 0, 0,
                                      (long long)DDIM*DDIM, 0, DDIM,
                                      DDIM, DDIM, 0);
    // 21. out = x @ Wf + bf   [2048,512] x8
    gemm128p2<<<dim3(4, 16, 8), 256>>>(x, 0, 0,
                                       Wf, bf, out, NOSET2,
                                       (long long)DDIM*DDIM, 0, DDIM,
                                       (long long)NTOK*DDIM, 0, DDIM,
                                       DDIM, DDIM, 0);
}

// round 5
// speedup vs baseline: 2.4180x; 1.3020x over previous
#include <cuda_runtime.h>
#include <cuda_bf16.h>
#include <stdint.h>

// ---- problem constants ----
#define NTOK 2048
#define DDIM 512
#define GRP  8
#define NQH  8
#define AD1  128
#define AD2  64

// ---- scratch (device globals: allocation-free) ----
__device__ float g_K1[GRP*NTOK*AD1];
__device__ float g_V1[GRP*NTOK*AD1];
__device__ float g_Sp[GRP*8*AD1*AD1];
__device__ float g_S1[GRP*AD1*AD1];
__device__ float g_P1[GRP*DDIM*NQH*AD1];
__device__ float g_bP1[GRP*NQH*AD1];
__device__ float g_W1[GRP*DDIM*DDIM];
__device__ float g_b1[GRP*DDIM];
__device__ float g_Wk2e[GRP*DDIM*AD2];
__device__ float g_Wv2e[GRP*DDIM*AD2];
__device__ float g_bk2e[GRP*AD2];
__device__ float g_bv2e[GRP*AD2];
__device__ float g_K2[GRP*NTOK*AD2];
__device__ float g_V2[GRP*NTOK*AD2];
__device__ float g_S2[GRP*AD2*AD2];
__device__ float g_bP2[GRP*NQH*AD2];
__device__ float g_P2[GRP*DDIM*NQH*AD2];
__device__ float g_b2[GRP*DDIM];
__device__ float g_W2[GRP*DDIM*DDIM];
__device__ float g_W23[GRP*DDIM*DDIM];
__device__ float g_Wf[GRP*DDIM*DDIM];
__device__ float g_b3[GRP*DDIM];
__device__ float g_bf[GRP*DDIM];

// ---- helpers ----
__device__ __forceinline__ uint32_t smem_u32(const void* p) {
    return (uint32_t)__cvta_generic_to_shared(p);
}
__device__ __forceinline__ uint32_t sw128(uint32_t off) {
    return off ^ ((off >> 3) & 0x70);
}
__device__ __forceinline__ uint32_t lds32(uint32_t a) {
    uint32_t v;
    asm volatile("ld.shared.b32 %0, [%1];" : "=r"(v) : "r"(a));
    return v;
}
__device__ __forceinline__ uint32_t lds32lo(uint32_t a) {  // lo plane at +16384
    uint32_t v;
    asm volatile("ld.shared.b32 %0, [%1+16384];" : "=r"(v) : "r"(a));
    return v;
}
__device__ __forceinline__ void sts128(uint32_t a, uint4 v) {
    asm volatile("st.shared.v4.b32 [%0], {%1,%2,%3,%4};"
                 :: "r"(a), "r"(v.x), "r"(v.y), "r"(v.z), "r"(v.w));
}
// split 8 fp32 into 8 bf16 hi + 8 bf16 lo, packed 16B each
__device__ __forceinline__ void split8(float4 f0, float4 f1, uint4& hi, uint4& lo) {
    float a[8] = {f0.x, f0.y, f0.z, f0.w, f1.x, f1.y, f1.z, f1.w};
    unsigned h[8], l[8];
#pragma unroll
    for (int i = 0; i < 8; i++) {
        __nv_bfloat16 bh = __float2bfloat16(a[i]);
        float r = a[i] - __bfloat162float(bh);
        __nv_bfloat16 bl = __float2bfloat16(r);
        h[i] = (unsigned)__bfloat16_as_ushort(bh);
        l[i] = (unsigned)__bfloat16_as_ushort(bl);
    }
    hi = make_uint4(h[0] | (h[1] << 16), h[2] | (h[3] << 16),
                    h[4] | (h[5] << 16), h[6] | (h[7] << 16));
    lo = make_uint4(l[0] | (l[1] << 16), l[2] | (l[3] << 16),
                    l[4] | (l[5] << 16), l[6] | (l[7] << 16));
}
#define MMA16816(c, a0, a1, a2, a3, b0, b1) \
    asm volatile( \
        "mma.sync.aligned.m16n8k16.row.col.f32.bf16.bf16.f32 " \
        "{%0,%1,%2,%3}, {%4,%5,%6,%7}, {%8,%9}, {%0,%1,%2,%3};" \
        : "+f"((c)[0]), "+f"((c)[1]), "+f"((c)[2]), "+f"((c)[3]) \
        : "r"(a0), "r"(a1), "r"(a2), "r"(a3), "r"(b0), "r"(b1))

// smem region: A_hi 0, A_lo 16K, B_hi 32K, B_lo 48K (+1K align slack)
#define OFF_B 32768
#define TG_SMEM (65536 + 1024)

// ============================================================================
// Batched tensor-core GEMM (bf16 hi/lo split, fp32 in/out):
// C[128, ntile] per CTA = A[M,K] @ B[K,N] (+bias).
// 256 threads = 8 warps (2 M x 4 N). K multiple of 64. ntile in {64,128}.
// Dual output set via blockIdx.z >= zsplit (fuses two GEMMs sharing A).
// ============================================================================
__global__ __launch_bounds__(256)
void tgemm(const float* __restrict__ A, long long aO, long long aI,
           const float* __restrict__ B, const float* __restrict__ bias,
           float* __restrict__ C,
           const float* __restrict__ B2, const float* __restrict__ bias2,
           float* __restrict__ C2, int zsplit,
           long long bO, long long bI, long long biasO,
           long long cO, long long cI, int ldc,
           int N, int K, int ntile, int bshift)
{
    extern __shared__ char smraw[];
    uint32_t sb0 = smem_u32(smraw);
    uint32_t abase = (sb0 + 1023) & ~1023u;

    int tid = threadIdx.x;
    int lane = tid & 31, w = tid >> 5;
    int gid = lane >> 2, tig = lane & 3;

    int z = blockIdx.z;
    const float* Bu = B; const float* biasu = bias; float* Cu = C;
    if (z >= zsplit) { z -= zsplit; Bu = B2; biasu = bias2; Cu = C2; }
    int bh = z >> bshift, bl = z & ((1 << bshift) - 1);
    const float* Ab = A + (long long)bh * aO + (long long)bl * aI;
    const float* Bb = Bu + (long long)bh * bO + (long long)bl * bI;
    float*       Cb = Cu + (long long)bh * cO + (long long)bl * cI;

    int m0 = blockIdx.y * 128;
    int n0b = blockIdx.x * ntile;

    int wm = w & 1, wn = w >> 1;
    int warp_m = wm * 64;
    int warp_n = wn * (ntile >> 2);
    int Ntiles = ntile >> 5;   // n8-tile pairs per warp: 2 (ntile64) or 4 (ntile128)

    float acc[4][4][4];
#pragma unroll
    for (int i = 0; i < 4; i++)
#pragma unroll
        for (int j = 0; j < 4; j++)
#pragma unroll
            for (int k = 0; k < 4; k++) acc[i][j][k] = 0.f;

    // fill-side indices
    int arow_f = tid >> 1;
    int akh = (tid & 1) * 32;
    const float* Ap = Ab + (long long)(m0 + arow_f) * K + akh;
    int tpn = 256 / ntile;              // threads per B column: 2 or 4
    int bn_f = tid / tpn;
    int bks = 64 / tpn;                 // k's per thread: 32 or 16
    int bk0 = (tid - bn_f * tpn) * bks;
    const float* Bp = Bb + n0b + bn_f;

    // compute-side smem bases (constant across chunks)
    uint32_t aB[4], bB[4];
#pragma unroll
    for (int mt = 0; mt < 4; mt++)
        aB[mt] = abase + (uint32_t)(warp_m + mt * 16 + gid) * 128;
#pragma unroll
    for (int nt = 0; nt < 4; nt++)
        bB[nt] = abase + OFF_B + (uint32_t)(warp_n + nt * 8 + gid) * 128;
    uint32_t rx = (uint32_t)gid << 4;

    int nchunk = K >> 6;
    for (int ch = 0; ch < nchunk; ch++) {
        int kc = ch << 6;
        if (ch) __syncthreads();   // previous compute done before overwrite
        // ---- A tile fill: row arow_f, k in [akh, akh+32) ----
        {
            uint32_t ro = (uint32_t)arow_f * 128;
#pragma unroll
            for (int k = 0; k < 32; k += 8) {
                float4 f0 = *(const float4*)(Ap + kc + k);
                float4 f1 = *(const float4*)(Ap + kc + k + 4);
                uint4 hi, lo;
                split8(f0, f1, hi, lo);
                uint32_t sw = abase + sw128(ro + (akh + k) * 2);
                sts128(sw, hi);
                sts128(sw + 16384, lo);
            }
        }
        // ---- B tile fill (transposed): col bn_f, k in [bk0, bk0+bks) ----
        {
            uint32_t ro = (uint32_t)bn_f * 128;
            for (int k = 0; k < bks; k += 8) {
                int kp = bk0 + k;
                float v[8];
#pragma unroll
                for (int i = 0; i < 8; i++)
                    v[i] = Bp[(long long)(kc + kp + i) * N];
                uint4 hi, lo;
                split8(make_float4(v[0], v[1], v[2], v[3]),
                       make_float4(v[4], v[5], v[6], v[7]), hi, lo);
                uint32_t sw = abase + OFF_B + sw128(ro + kp * 2);
                sts128(sw, hi);
                sts128(sw + 16384, lo);
            }
        }
        __syncthreads();

        // ---- compute: 4 k16 steps ----
#pragma unroll
        for (int ks = 0; ks < 4; ks++) {
            uint32_t q0 = ((uint32_t)(ks * 32) + (uint32_t)tig * 4) ^ rx;
            uint32_t q1 = q0 ^ 16;
            uint32_t ah[4][4], al[4][4];
#pragma unroll
            for (int mt = 0; mt < 4; mt++) {
                uint32_t base = aB[mt];
                ah[mt][0] = lds32(base + q0);
                ah[mt][1] = lds32(base + 1024 + q0);
                ah[mt][2] = lds32(base + q1);
                ah[mt][3] = lds32(base + 1024 + q1);
                al[mt][0] = lds32lo(base + q0);
                al[mt][1] = lds32lo(base + 1024 + q0);
                al[mt][2] = lds32lo(base + q1);
                al[mt][3] = lds32lo(base + 1024 + q1);
            }
#pragma unroll
            for (int nt = 0; nt < 4; nt++) {
                if (nt >= Ntiles) break;
                uint32_t bb = bB[nt];
                uint32_t bh0 = lds32(bb + q0);
                uint32_t bh1 = lds32(bb + q1);
                uint32_t bl0 = lds32lo(bb + q0);
                uint32_t bl1 = lds32lo(bb + q1);
#pragma unroll
                for (int mt = 0; mt < 4; mt++) {
                    MMA16816(acc[mt][nt], ah[mt][0], ah[mt][1], ah[mt][2], ah[mt][3], bh0, bh1);
                    MMA16816(acc[mt][nt], ah[mt][0], ah[mt][1], ah[mt][2], ah[mt][3], bl0, bl1);
                    MMA16816(acc[mt][nt], al[mt][0], al[mt][1], al[mt][2], al[mt][3], bh0, bh1);
                }
            }
        }
    }

    // ---- epilogue ----
    const float* bp = biasu ? (biasu + (long long)bh * biasO + n0b) : (const float*)nullptr;
#pragma unroll
    for (int mt = 0; mt < 4; mt++) {
        long long r0 = m0 + warp_m + mt * 16 + gid;
#pragma unroll
        for (int nt = 0; nt < 4; nt++) {
            if (nt >= Ntiles) break;
            int cc = warp_n + nt * 8 + 2 * tig;
            float b0 = 0.f, b1 = 0.f;
            if (bp) { b0 = bp[cc]; b1 = bp[cc + 1]; }
            float2 v0 = make_float2(acc[mt][nt][0] + b0, acc[mt][nt][1] + b1);
            float2 v1 = make_float2(acc[mt][nt][2] + b0, acc[mt][nt][3] + b1);
            *(float2*)&Cb[r0 * ldc + n0b + cc]       = v0;
            *(float2*)&Cb[(r0 + 8) * ldc + n0b + cc] = v1;
        }
    }
}

// ============================================================================
// Split-K TN GEMM partials (fp32, Gram matrices): Cp[z] = A_slice^T @ B_slice
// ============================================================================
__global__ __launch_bounds__(256)
void gemm_tn_sk(const float* __restrict__ A, long long aO,
                const float* __restrict__ B, long long bO,
                float* __restrict__ Cp, int M, int N, int Ktot)
{
    int z = blockIdx.z;
    int g = z >> 3, c = z & 7;
    int kl = Ktot >> 3;
    const float* Ab = A + (long long)g * aO + (long long)c * kl * M;
    const float* Bb = B + (long long)g * bO + (long long)c * kl * N;
    float*       Cb = Cp + (long long)z * M * N;

    __shared__ __align__(16) float As[16][64];
    __shared__ __align__(16) float Bs[16][64];

    int tid = threadIdx.x;
    int m0 = blockIdx.y * 64;
    int n0 = blockIdx.x * 64;

    int lrow = tid >> 4;
    int lcol = (tid & 15) * 4;
    int tx = tid & 15;
    int ty = tid >> 4;

    const float* Ap = Ab + (long long)lrow * M + m0 + lcol;
    const float* Bp = Bb + (long long)lrow * N + n0 + lcol;

    float acc[4][4];
#pragma unroll
    for (int i = 0; i < 4; i++)
#pragma unroll
        for (int j = 0; j < 4; j++) acc[i][j] = 0.f;

    for (int k0 = 0; k0 < kl; k0 += 16) {
        *(float4*)&As[lrow][lcol] = *(const float4*)(Ap + (long long)k0 * M);
        *(float4*)&Bs[lrow][lcol] = *(const float4*)(Bp + (long long)k0 * N);
        __syncthreads();
#pragma unroll
        for (int kk = 0; kk < 16; kk++) {
            float4 a = *(const float4*)&As[kk][ty * 4];
            float4 bb4 = *(const float4*)&Bs[kk][tx * 4];
            float a4[4] = {a.x, a.y, a.z, a.w};
            float b4[4] = {bb4.x, bb4.y, bb4.z, bb4.w};
#pragma unroll
            for (int i = 0; i < 4; i++)
#pragma unroll
                for (int j = 0; j < 4; j++)
                    acc[i][j] = fmaf(a4[i], b4[j], acc[i][j]);
        }
        __syncthreads();
    }

#pragma unroll
    for (int i = 0; i < 4; i++) {
        int row = m0 + ty * 4 + i;
        float4 v = {acc[i][0], acc[i][1], acc[i][2], acc[i][3]};
        *(float4*)&Cb[(long long)row * N + n0 + tx * 4] = v;
    }
}

__global__ void reduce8(const float* __restrict__ Cp, float* __restrict__ C,
                        float alpha, int MN)
{
    int i = blockIdx.x * 256 + threadIdx.x;
    int g = blockIdx.y;
    const float* p = Cp + (long long)g * 8 * MN + i;
    float s = 0.f;
#pragma unroll
    for (int c = 0; c < 8; c++) s += p[(long long)c * MN];
    C[(long long)g * MN + i] = alpha * s;
}

// ============================================================================
// Batched vec @ mat, in-block K-split; dual-set via blockIdx.y >= ysplit.
// ============================================================================
__global__ __launch_bounds__(256)
void vecmat2(const float* __restrict__ vec, long long vecStride,
             const float* __restrict__ mat, long long matO, long long matI, int bshift,
             const float* __restrict__ add, long long addStride,
             float* __restrict__ out, long long outStride,
             const float* __restrict__ vec2, const float* __restrict__ mat2,
             const float* __restrict__ add2, float* __restrict__ out2,
             int ysplit, int K, int N)
{
    int b = blockIdx.y;
    const float* vecu = vec; const float* matu = mat;
    const float* addu = add; float* outu = out;
    if (b >= ysplit) { b -= ysplit; vecu = vec2; matu = mat2; addu = add2; outu = out2; }
    int c = (threadIdx.x & 63) + blockIdx.x * 64;
    int s = threadIdx.x >> 6;
    const float* v = vecu + (long long)b * vecStride;
    const float* m = matu + (long long)(b >> bshift) * matO
                          + (long long)(b & ((1 << bshift) - 1)) * matI;
    int kpart = K >> 2;
    int kb = s * kpart;
    float acc = 0.f;
    if (c < N)
        for (int k = 0; k < kpart; k++)
            acc = fmaf(v[kb + k], m[(long long)(kb + k) * N + c], acc);

    __shared__ float red[256];
    red[threadIdx.x] = acc;
    __syncthreads();
    if (s == 0 && c < N) {
        float t = red[threadIdx.x] + red[threadIdx.x + 64]
                + red[threadIdx.x + 128] + red[threadIdx.x + 192];
        if (addu) t += addu[(long long)b * addStride + c];
        outu[(long long)b * outStride + c] = t;
    }
}

#define NOSET2 (const float*)nullptr, (const float*)nullptr, (float*)nullptr, (1<<30)
#define NOVEC2 nullptr, nullptr, nullptr, nullptr, (1<<30)

extern "C" void kernel_launch(void* const* d_in, const int* in_sizes, int n_in,
                              void* d_out, int out_size)
{
    (void)in_sizes; (void)n_in; (void)out_size;

    const float* x   = (const float*)d_in[0];
    const float* Wq1 = (const float*)d_in[1];
    const float* bq1 = (const float*)d_in[2];
    const float* Wk1 = (const float*)d_in[3];
    const float* bk1 = (const float*)d_in[4];
    const float* Wv1 = (const float*)d_in[5];
    const float* bv1 = (const float*)d_in[6];
    const float* Wo1 = (const float*)d_in[7];
    const float* bo1 = (const float*)d_in[8];
    const float* Wq2 = (const float*)d_in[9];
    const float* bq2 = (const float*)d_in[10];
    const float* Wk2 = (const float*)d_in[11];
    const float* bk2 = (const float*)d_in[12];
    const float* Wv2 = (const float*)d_in[13];
    const float* bv2 = (const float*)d_in[14];
    const float* Wo2 = (const float*)d_in[15];
    const float* bo2 = (const float*)d_in[16];
    const float* Wo  = (const float*)d_in[17];
    const float* bo  = (const float*)d_in[18];
    float* out = (float*)d_out;

    float *K1, *V1, *Sp, *S1, *P1, *bP1, *W1, *b1;
    float *Wk2e, *Wv2e, *bk2e, *bv2e, *K2, *V2, *S2, *bP2, *P2, *b2;
    float *W2, *W23, *Wf, *b3, *bf;
    cudaGetSymbolAddress((void**)&K1,   g_K1);
    cudaGetSymbolAddress((void**)&V1,   g_V1);
    cudaGetSymbolAddress((void**)&Sp,   g_Sp);
    cudaGetSymbolAddress((void**)&S1,   g_S1);
    cudaGetSymbolAddress((void**)&P1,   g_P1);
    cudaGetSymbolAddress((void**)&bP1,  g_bP1);
    cudaGetSymbolAddress((void**)&W1,   g_W1);
    cudaGetSymbolAddress((void**)&b1,   g_b1);
    cudaGetSymbolAddress((void**)&Wk2e, g_Wk2e);
    cudaGetSymbolAddress((void**)&Wv2e, g_Wv2e);
    cudaGetSymbolAddress((void**)&bk2e, g_bk2e);
    cudaGetSymbolAddress((void**)&bv2e, g_bv2e);
    cudaGetSymbolAddress((void**)&K2,   g_K2);
    cudaGetSymbolAddress((void**)&V2,   g_V2);
    cudaGetSymbolAddress((void**)&S2,   g_S2);
    cudaGetSymbolAddress((void**)&bP2,  g_bP2);
    cudaGetSymbolAddress((void**)&P2,   g_P2);
    cudaGetSymbolAddress((void**)&b2,   g_b2);
    cudaGetSymbolAddress((void**)&W2,   g_W2);
    cudaGetSymbolAddress((void**)&W23,  g_W23);
    cudaGetSymbolAddress((void**)&Wf,   g_Wf);
    cudaGetSymbolAddress((void**)&b3,   g_b3);
    cudaGetSymbolAddress((void**)&bf,   g_bf);

    cudaFuncSetAttribute(tgemm, cudaFuncAttributeMaxDynamicSharedMemorySize, TG_SMEM);

    const float inv_sa1 = 0.08838834764831845f;  // 1/sqrt(128)
    const float inv_sa2 = 0.125f;                // 1/sqrt(64)

    // 1. K1 & V1 fused: [2048,128] = x @ Wk1/Wv1 + bias
    tgemm<<<dim3(1, 16, 16), 256, TG_SMEM>>>(x, 0, 0,
        Wk1, bk1, K1, Wv1, bv1, V1, 8,
        (long long)DDIM*AD1, 0, AD1,
        (long long)NTOK*AD1, 0, AD1, AD1, DDIM, 128, 0);
    // 2-3. S1 = K1^T V1 / sqrt(A1), split-K x8 + reduce
    gemm_tn_sk<<<dim3(2, 2, 64), 256>>>(K1, (long long)NTOK*AD1,
                                        V1, (long long)NTOK*AD1,
                                        Sp, AD1, AD1, NTOK);
    reduce8<<<dim3(64, 8), 256>>>(Sp, S1, inv_sa1, AD1*AD1);
    // 4. bP1
    vecmat2<<<dim3(2, 64), 256>>>(bq1, AD1, S1, (long long)AD1*AD1, 0, 3,
                                  (const float*)nullptr, 0, bP1, AD1,
                                  NOVEC2, AD1, AD1);
    // 5. P1cat = Wq1[g,q] @ S1[g]  [512,128] x64
    tgemm<<<dim3(1, 4, 64), 256, TG_SMEM>>>(Wq1, (long long)NQH*DDIM*AD1, (long long)DDIM*AD1,
        S1, (const float*)nullptr, P1, NOSET2,
        (long long)AD1*AD1, 0, 0,
        (long long)DDIM*NQH*AD1, AD1, NQH*AD1, AD1, AD1, 128, 3);
    // 6. b1 = bP1 @ Wo1 + bo1
    vecmat2<<<dim3(8, 8), 256>>>(bP1, NQH*AD1, Wo1, (long long)NQH*AD1*DDIM, 0, 0,
                                 bo1, DDIM, b1, DDIM, NOVEC2, NQH*AD1, DDIM);
    // 7. W1 = P1cat @ Wo1  [512,512] K=1024
    tgemm<<<dim3(4, 4, 8), 256, TG_SMEM>>>(P1, (long long)DDIM*NQH*AD1, 0,
        Wo1, (const float*)nullptr, W1, NOSET2,
        (long long)NQH*AD1*DDIM, 0, 0,
        (long long)DDIM*DDIM, 0, DDIM, DDIM, NQH*AD1, 128, 0);
    // 8. Wk2e & Wv2e fused: W1 @ Wk2/Wv2  [512,64]
    tgemm<<<dim3(1, 4, 16), 256, TG_SMEM>>>(W1, (long long)DDIM*DDIM, 0,
        Wk2, (const float*)nullptr, Wk2e,
        Wv2, (const float*)nullptr, Wv2e, 8,
        (long long)DDIM*AD2, 0, 0,
        (long long)DDIM*AD2, 0, AD2, AD2, DDIM, 64, 0);
    // 9. bk2e & bv2e fused
    vecmat2<<<dim3(1, 16), 256>>>(b1, DDIM, Wk2, (long long)DDIM*AD2, 0, 0,
                                  bk2, AD2, bk2e, AD2,
                                  b1, Wv2, bv2, bv2e, 8, DDIM, AD2);
    // 10. K2 & V2 fused: x @ Wk2e/Wv2e + bias  [2048,64]
    tgemm<<<dim3(1, 16, 16), 256, TG_SMEM>>>(x, 0, 0,
        Wk2e, bk2e, K2, Wv2e, bv2e, V2, 8,
        (long long)DDIM*AD2, 0, AD2,
        (long long)NTOK*AD2, 0, AD2, AD2, DDIM, 64, 0);
    // 11-12. S2 split-K + reduce
    gemm_tn_sk<<<dim3(1, 1, 64), 256>>>(K2, (long long)NTOK*AD2,
                                        V2, (long long)NTOK*AD2,
                                        Sp, AD2, AD2, NTOK);
    reduce8<<<dim3(16, 8), 256>>>(Sp, S2, inv_sa2, AD2*AD2);
    // 13. bP2
    vecmat2<<<dim3(1, 64), 256>>>(bq2, AD2, S2, (long long)AD2*AD2, 0, 3,
                                  (const float*)nullptr, 0, bP2, AD2,
                                  NOVEC2, AD2, AD2);
    // 14. P2cat = Wq2[g,q] @ S2[g]  [512,64] x64
    tgemm<<<dim3(1, 4, 64), 256, TG_SMEM>>>(Wq2, (long long)NQH*DDIM*AD2, (long long)DDIM*AD2,
        S2, (const float*)nullptr, P2, NOSET2,
        (long long)AD2*AD2, 0, 0,
        (long long)DDIM*NQH*AD2, AD2, NQH*AD2, AD2, AD2, 64, 3);
    // 15. b2 = bP2 @ Wo2 + bo2
    vecmat2<<<dim3(8, 8), 256>>>(bP2, NQH*AD2, Wo2, (long long)NQH*AD2*DDIM, 0, 0,
                                 bo2, DDIM, b2, DDIM, NOVEC2, NQH*AD2, DDIM);
    // 16. W2 = P2cat @ Wo2  [512,512] K=512
    tgemm<<<dim3(4, 4, 8), 256, TG_SMEM>>>(P2, (long long)DDIM*NQH*AD2, 0,
        Wo2, (const float*)nullptr, W2, NOSET2,
        (long long)NQH*AD2*DDIM, 0, 0,
        (long long)DDIM*DDIM, 0, DDIM, DDIM, NQH*AD2, 128, 0);
    // 17. W23 = W2 @ Wo
    tgemm<<<dim3(4, 4, 8), 256, TG_SMEM>>>(W2, (long long)DDIM*DDIM, 0,
        Wo, (const float*)nullptr, W23, NOSET2,
        0, 0, 0,
        (long long)DDIM*DDIM, 0, DDIM, DDIM, DDIM, 128, 0);
    // 18. b3 = b2 @ Wo + bo
    vecmat2<<<dim3(8, 8), 256>>>(b2, DDIM, Wo, 0, 0, 0,
                                 bo, 0, b3, DDIM, NOVEC2, DDIM, DDIM);
    // 19. bf = b1 @ W23 + b3
    vecmat2<<<dim3(8, 8), 256>>>(b1, DDIM, W23, (long long)DDIM*DDIM, 0, 0,
                                 b3, DDIM, bf, DDIM, NOVEC2, DDIM, DDIM);
    // 20. Wf = W1 @ W23
    tgemm<<<dim3(4, 4, 8), 256, TG_SMEM>>>(W1, (long long)DDIM*DDIM, 0,
        W23, (const float*)nullptr, Wf, NOSET2,
        (long long)DDIM*DDIM, 0, 0,
        (long long)DDIM*DDIM, 0, DDIM, DDIM, DDIM, 128, 0);
    // 21. out = x @ Wf + bf  [2048,512] x8
    tgemm<<<dim3(4, 16, 8), 256, TG_SMEM>>>(x, 0, 0,
        Wf, bf, out, NOSET2,
        (long long)DDIM*DDIM, 0, DDIM,
        (long long)NTOK*DDIM, 0, DDIM, DDIM, DDIM, 128, 0);
}